// round 1
// baseline (speedup 1.0000x reference)
#include <cuda_runtime.h>

#define E_ 64
#define D_ 128
#define K_ 4
#define B_ 2
#define H_ 96
#define W_ 96
#define HW_ (H_*W_)
#define PAD_ 128

// ---------------- scratch (static device globals; zero-initialized) ----------------
__device__ float g_keys[K_*B_*E_*HW_ + 2*PAD_];   // keys, pixel-plane padded for halo reads
__device__ float g_proj[K_*B_*E_*HW_ + 2*PAD_];   // W_attn[k+1] @ ctx
__device__ float g_q   [B_*E_*HW_];               // queries
__device__ float g_pv  [B_*E_*HW_];               // W_attn[0] @ values (conv output, projected)
__device__ float g_p   [B_*HW_*36];               // softmax probs [pix][k*9+n]
__device__ float g_wveff[E_*D_*9];                // (W_attn_v @ w_val)
__device__ float g_bveff[E_];                     // (W_attn_v @ b_val)

__device__ __forceinline__ float tanh_fast(float x) {
    x = fminf(10.0f, fmaxf(-10.0f, x));
    float e = __expf(2.0f * x);
    return __fdividef(e - 1.0f, e + 1.0f);
}

__device__ __forceinline__ void fma4(float4& a, float w, const float4& x) {
    a.x = fmaf(w, x.x, a.x); a.y = fmaf(w, x.y, a.y);
    a.z = fmaf(w, x.z, a.z); a.w = fmaf(w, x.w, a.w);
}

// ---------------- prep: fold w_attn value-block into conv weights ----------------
__global__ void prep_wveff(const float* __restrict__ w_attn, const float* __restrict__ w_val) {
    int o = blockIdx.x * 256 + threadIdx.x;          // 73728 total, exact
    int eo = o / (D_*9);
    int r  = o - eo * (D_*9);
    const float* wa = w_attn + eo * ((K_+1)*E_);
    float a = 0.f;
    #pragma unroll 8
    for (int e = 0; e < E_; e++) a = fmaf(wa[e], w_val[e*(D_*9) + r], a);
    g_wveff[o] = a;
}

__global__ void prep_bveff(const float* __restrict__ w_attn, const float* __restrict__ b_val) {
    int eo = threadIdx.x;
    const float* wa = w_attn + eo * ((K_+1)*E_);
    float a = 0.f;
    for (int e = 0; e < E_; e++) a = fmaf(wa[e], b_val[e], a);
    g_bveff[eo] = a;
}

// ---------------- queries: g_q = w_dec @ df + b_dec ----------------
// grid (72, B), block 256, dyn smem 96KB
__global__ void queries_kernel(const float* __restrict__ df,
                               const float* __restrict__ w_dec,
                               const float* __restrict__ b_dec) {
    extern __shared__ float sm[];
    float* xs = sm;              // [128 c][128 pix]
    float* wT = sm + D_*128;     // [128 c][64 e]
    int b = blockIdx.y, pix0 = blockIdx.x * 128, tid = threadIdx.x;

    for (int i = tid; i < D_*32; i += 256) {
        int c = i >> 5, gq = i & 31;
        *(float4*)&xs[c*128 + gq*4] = *(const float4*)&df[(b*D_ + c)*HW_ + pix0 + gq*4];
    }
    for (int i = tid; i < D_*E_; i += 256) {
        int e = i & 63, c = i >> 6;
        wT[c*64 + e] = w_dec[e*D_ + c];
    }
    __syncthreads();

    int ty = tid >> 5, lane = tid & 31, e0 = ty * 8;
    float4 acc[8];
    #pragma unroll
    for (int j = 0; j < 8; j++) acc[j] = make_float4(0.f,0.f,0.f,0.f);

    for (int c = 0; c < D_; c++) {
        float4 xv = *(const float4*)&xs[c*128 + lane*4];
        const float* wr = &wT[c*64 + e0];
        float4 wA = *(const float4*)wr, wB = *(const float4*)(wr + 4);
        fma4(acc[0], wA.x, xv); fma4(acc[1], wA.y, xv);
        fma4(acc[2], wA.z, xv); fma4(acc[3], wA.w, xv);
        fma4(acc[4], wB.x, xv); fma4(acc[5], wB.y, xv);
        fma4(acc[6], wB.z, xv); fma4(acc[7], wB.w, xv);
    }
    #pragma unroll
    for (int j = 0; j < 8; j++) {
        float bb = __ldg(&b_dec[e0 + j]);
        float4 v = acc[j];
        v.x += bb; v.y += bb; v.z += bb; v.w += bb;
        *(float4*)&g_q[(b*E_ + e0 + j)*HW_ + pix0 + lane*4] = v;
    }
}

// ---------------- keys + proj: two fused 64x64 GEMMs over ctx ----------------
// grid (72, K*B), block 256, dyn smem 64KB
__global__ void keysproj_kernel(const float* __restrict__ contexts,
                                const float* __restrict__ w_enc,
                                const float* __restrict__ b_enc,
                                const float* __restrict__ w_attn) {
    extern __shared__ float sm[];
    float* xs  = sm;                 // [64 c][128 pix]
    float* wkT = sm + E_*128;        // [64 c][64 e]
    float* wpT = wkT + E_*E_;
    int kb = blockIdx.y, k = kb >> 1, pix0 = blockIdx.x * 128, tid = threadIdx.x;

    for (int i = tid; i < E_*32; i += 256) {
        int c = i >> 5, gq = i & 31;
        *(float4*)&xs[c*128 + gq*4] = *(const float4*)&contexts[(kb*E_ + c)*HW_ + pix0 + gq*4];
    }
    for (int i = tid; i < E_*E_; i += 256) {
        int e = i & 63, c = i >> 6;
        wkT[c*64 + e] = w_enc[e*E_ + c];
        wpT[c*64 + e] = w_attn[e*((K_+1)*E_) + (k+1)*E_ + c];
    }
    __syncthreads();

    int ty = tid >> 5, lane = tid & 31;
    bool isp = ty >= 4;
    int e0 = (ty & 3) * 16;
    const float* wsrc = isp ? wpT : wkT;
    float* dst = isp ? g_proj : g_keys;

    float4 acc[16];
    #pragma unroll
    for (int j = 0; j < 16; j++) acc[j] = make_float4(0.f,0.f,0.f,0.f);

    for (int c = 0; c < E_; c++) {
        float4 xv = *(const float4*)&xs[c*128 + lane*4];
        const float* wr = &wsrc[c*64 + e0];
        #pragma unroll
        for (int jq = 0; jq < 4; jq++) {
            float4 wq = *(const float4*)(wr + jq*4);
            fma4(acc[jq*4+0], wq.x, xv); fma4(acc[jq*4+1], wq.y, xv);
            fma4(acc[jq*4+2], wq.z, xv); fma4(acc[jq*4+3], wq.w, xv);
        }
    }
    #pragma unroll
    for (int j = 0; j < 16; j++) {
        float bb = isp ? 0.f : __ldg(&b_enc[e0 + j]);
        float4 v = acc[j];
        v.x += bb; v.y += bb; v.z += bb; v.w += bb;
        *(float4*)&dst[PAD_ + (kb*E_ + e0 + j)*HW_ + pix0 + lane*4] = v;
    }
}

// ---------------- conv 3x3: pv = wveff (*) df + bveff ----------------
// grid (3, 24, B), block 256 (=128 pixels x 2 eo-halves), dyn smem 62KB
__global__ void conv_kernel(const float* __restrict__ df) {
    extern __shared__ float sm[];
    float* xs = sm;          // [16 d][6 rows][34 cols] = 3264
    float* ws = sm + 3264;   // [16 d][64 eo][12] = 12288
    int b = blockIdx.z, w0 = blockIdx.x * 32, h0 = blockIdx.y * 4;
    int tid = threadIdx.x;
    int px = tid & 31, py = (tid >> 5) & 3, grp = tid >> 7;

    float acc[32];
    #pragma unroll
    for (int j = 0; j < 32; j++) acc[j] = 0.f;

    for (int d0 = 0; d0 < D_; d0 += 16) {
        __syncthreads();
        for (int i = tid; i < 3264; i += 256) {
            int d = i / 204, r = i - d*204;
            int yy = r / 34, xx = r - yy*34;
            int gh = h0 + yy - 1, gw = w0 + xx - 1;
            float v = 0.f;
            if ((unsigned)gh < H_ && (unsigned)gw < W_)
                v = df[(b*D_ + d0 + d)*HW_ + gh*W_ + gw];
            xs[i] = v;
        }
        for (int i = tid; i < 12288; i += 256) {
            int d = i / 768, r = i - d*768;
            int eo = r / 12, tt = r - eo*12;
            ws[i] = (tt < 9) ? g_wveff[eo*(D_*9) + (d0 + d)*9 + tt] : 0.f;
        }
        __syncthreads();

        for (int d = 0; d < 16; d++) {
            const float* xr = &xs[d*204 + py*34 + px];
            float x0 = xr[0],  x1 = xr[1],  x2 = xr[2];
            float x3 = xr[34], x4 = xr[35], x5 = xr[36];
            float x6 = xr[68], x7 = xr[69], x8 = xr[70];
            const float* wbase = &ws[d*768 + grp*32*12];
            #pragma unroll
            for (int j = 0; j < 32; j++) {
                const float* wp = wbase + j*12;
                float4 wa = *(const float4*)wp;
                float4 wb = *(const float4*)(wp + 4);
                float w8v = wp[8];
                float a = acc[j];
                a = fmaf(x0, wa.x, a); a = fmaf(x1, wa.y, a); a = fmaf(x2, wa.z, a);
                a = fmaf(x3, wa.w, a); a = fmaf(x4, wb.x, a); a = fmaf(x5, wb.y, a);
                a = fmaf(x6, wb.z, a); a = fmaf(x7, wb.w, a); a = fmaf(x8, w8v, a);
                acc[j] = a;
            }
        }
    }
    int pix = (h0 + py)*W_ + w0 + px;
    #pragma unroll
    for (int j = 0; j < 32; j++) {
        int eo = grp*32 + j;
        g_pv[(b*E_ + eo)*HW_ + pix] = acc[j] + g_bveff[eo];
    }
}

// ---------------- attention scores + softmax ----------------
// grid 288, block 256: one thread per (k,b,pixel)
__global__ void attn_kernel(const float* __restrict__ w_agg) {
    int id = blockIdx.x * 256 + threadIdx.x;    // 73728 exact
    int kb = id / HW_;
    int pix = id - kb * HW_;
    int b = kb & 1;
    int h = pix / W_, w = pix - h*W_;

    const int off[9] = {-W_-1, -W_, -W_+1, -1, 0, 1, W_-1, W_, W_+1};
    const float* qb   = g_q    + (b*E_)*HW_ + pix;
    const float* keyb = g_keys + PAD_ + (kb*E_)*HW_ + pix;

    float s[9];
    #pragma unroll
    for (int n = 0; n < 9; n++) s[n] = 0.f;

    #pragma unroll 2
    for (int e = 0; e < E_; e++) {
        float q  = __ldg(qb + e*HW_);
        float wa = __ldg(w_agg + e);
        const float* kp = keyb + e*HW_;
        #pragma unroll
        for (int n = 0; n < 9; n++) {
            float t = tanh_fast(q + __ldg(kp + off[n]));
            s[n] = fmaf(wa, t, s[n]);
        }
    }
    bool vt = h > 0, vb = h < H_-1, vl = w > 0, vr = w < W_-1;
    bool valid[9] = {vt&&vl, vt, vt&&vr, vl, true, vr, vb&&vl, vb, vb&&vr};
    #pragma unroll
    for (int n = 0; n < 9; n++) if (!valid[n]) s[n] = -1e30f;
    float m = s[0];
    #pragma unroll
    for (int n = 1; n < 9; n++) m = fmaxf(m, s[n]);
    float p[9], sum = 0.f;
    #pragma unroll
    for (int n = 0; n < 9; n++) { p[n] = __expf(s[n] - m); sum += p[n]; }
    float inv = 1.0f / sum;
    float* pd = g_p + (b*HW_ + pix)*36 + (kb >> 1)*9;
    #pragma unroll
    for (int n = 0; n < 9; n++) pd[n] = p[n] * inv;
}

// ---------------- output: pv + sum_k sum_n p * proj, bias, leaky ----------------
// grid 576, block 256 (=32 pixels x 8 eo-octets)
__global__ void out_kernel(const float* __restrict__ b_attn, float* __restrict__ out) {
    __shared__ float sp[32][37];
    int tid = threadIdx.x;
    int pixg0 = blockIdx.x * 32;
    int pl = tid & 31, ty = tid >> 5;

    for (int i = tid; i < 32*36; i += 256) {
        int a = i / 36, j = i - a*36;
        sp[a][j] = g_p[(pixg0 + a)*36 + j];
    }
    __syncthreads();

    int pg = pixg0 + pl;
    int b = pg / HW_;
    int pix = pg - b*HW_;
    int eo0 = ty * 8;
    const int off[9] = {-W_-1, -W_, -W_+1, -1, 0, 1, W_-1, W_, W_+1};

    float acc[8];
    #pragma unroll
    for (int j = 0; j < 8; j++) acc[j] = __ldg(&g_pv[(b*E_ + eo0 + j)*HW_ + pix]);

    #pragma unroll
    for (int k = 0; k < K_; k++) {
        const float* prb = g_proj + PAD_ + ((k*B_ + b)*E_ + eo0)*HW_ + pix;
        #pragma unroll
        for (int n = 0; n < 9; n++) {
            float pn = sp[pl][k*9 + n];
            int o = off[n];
            #pragma unroll
            for (int j = 0; j < 8; j++)
                acc[j] = fmaf(pn, __ldg(prb + j*HW_ + o), acc[j]);
        }
    }
    #pragma unroll
    for (int j = 0; j < 8; j++) {
        float v = acc[j] + __ldg(&b_attn[eo0 + j]);
        v = (v >= 0.f) ? v : 0.2f * v;
        out[(b*E_ + eo0 + j)*HW_ + pix] = v;
    }
}

// ---------------- launch ----------------
extern "C" void kernel_launch(void* const* d_in, const int* in_sizes, int n_in,
                              void* d_out, int out_size) {
    const float* contexts = (const float*)d_in[0];
    const float* df       = (const float*)d_in[1];
    const float* w_enc    = (const float*)d_in[2];
    const float* b_enc    = (const float*)d_in[3];
    const float* w_dec    = (const float*)d_in[4];
    const float* b_dec    = (const float*)d_in[5];
    const float* w_agg    = (const float*)d_in[6];
    // d_in[7] = b_agg: cancels in softmax, unused
    const float* w_val    = (const float*)d_in[8];
    const float* b_val    = (const float*)d_in[9];
    const float* w_attn   = (const float*)d_in[10];
    const float* b_attn   = (const float*)d_in[11];
    float* out = (float*)d_out;

    cudaFuncSetAttribute(queries_kernel,  cudaFuncAttributeMaxDynamicSharedMemorySize, (D_*128 + D_*E_)*4);
    cudaFuncSetAttribute(keysproj_kernel, cudaFuncAttributeMaxDynamicSharedMemorySize, (E_*128 + 2*E_*E_)*4);
    cudaFuncSetAttribute(conv_kernel,     cudaFuncAttributeMaxDynamicSharedMemorySize, (3264 + 12288)*4);

    prep_wveff<<<288, 256>>>(w_attn, w_val);
    prep_bveff<<<1, 64>>>(w_attn, b_val);
    queries_kernel<<<dim3(HW_/128, B_), 256, (D_*128 + D_*E_)*4>>>(df, w_dec, b_dec);
    keysproj_kernel<<<dim3(HW_/128, K_*B_), 256, (E_*128 + 2*E_*E_)*4>>>(contexts, w_enc, b_enc, w_attn);
    conv_kernel<<<dim3(3, 24, B_), 256, (3264 + 12288)*4>>>(df);
    attn_kernel<<<288, 256>>>(w_agg);
    out_kernel<<<(B_*HW_)/32, 256>>>(b_attn, out);
}

// round 2
// speedup vs baseline: 1.3362x; 1.3362x over previous
#include <cuda_runtime.h>

#define E_ 64
#define D_ 128
#define K_ 4
#define B_ 2
#define H_ 96
#define W_ 96
#define HW_ (H_*W_)
#define PAD_ 128

typedef unsigned long long ull;

// ---------------- scratch (static device globals) ----------------
__device__ float g_keys[K_*B_*E_*HW_ + 2*PAD_];
__device__ float g_proj[K_*B_*E_*HW_ + 2*PAD_];
__device__ float g_q   [B_*E_*HW_];
__device__ float g_pvh [2*B_*E_*HW_];             // conv partials, 2 D-halves
__device__ float g_p   [B_*HW_*36];
__device__ float g_wveff[E_*D_*9];
__device__ float g_bveff[E_];

// ---------------- packed f32x2 helpers ----------------
__device__ __forceinline__ ull pack2(float x, float y) {
    ull r; asm("mov.b64 %0, {%1, %2};" : "=l"(r) : "f"(x), "f"(y)); return r;
}
__device__ __forceinline__ ull dup2(float x) { return pack2(x, x); }
__device__ __forceinline__ void fma2(ull& d, ull a, ull b) {
    asm("fma.rn.f32x2 %0, %1, %2, %0;" : "+l"(d) : "l"(a), "l"(b));
}
__device__ __forceinline__ float2 unpack2(ull v) {
    float2 r; asm("mov.b64 {%0, %1}, %2;" : "=f"(r.x), "=f"(r.y) : "l"(v)); return r;
}
__device__ __forceinline__ float tanh_hw(float x) {
    float r; asm("tanh.approx.f32 %0, %1;" : "=f"(r) : "f"(x)); return r;
}

// ---------------- prep: fold w_attn value-block into conv weights ----------------
__global__ void prep_wveff(const float* __restrict__ w_attn, const float* __restrict__ w_val) {
    int o = blockIdx.x * 256 + threadIdx.x;          // 73728 total, exact
    int eo = o / (D_*9);
    int r  = o - eo * (D_*9);
    const float* wa = w_attn + eo * ((K_+1)*E_);
    float a = 0.f;
    #pragma unroll 8
    for (int e = 0; e < E_; e++) a = fmaf(wa[e], w_val[e*(D_*9) + r], a);
    g_wveff[o] = a;
}

__global__ void prep_bveff(const float* __restrict__ w_attn, const float* __restrict__ b_val) {
    int eo = threadIdx.x;
    const float* wa = w_attn + eo * ((K_+1)*E_);
    float a = 0.f;
    for (int e = 0; e < E_; e++) a = fmaf(wa[e], b_val[e], a);
    g_bveff[eo] = a;
}

// ---------------- queries: g_q = w_dec @ df + b_dec ----------------
// grid (72, B), block 256, dyn smem 96KB
__global__ void queries_kernel(const float* __restrict__ df,
                               const float* __restrict__ w_dec,
                               const float* __restrict__ b_dec) {
    extern __shared__ float sm[];
    float* xs = sm;              // [128 c][128 pix]
    float* wT = sm + D_*128;     // [128 c][64 e]
    int b = blockIdx.y, pix0 = blockIdx.x * 128, tid = threadIdx.x;

    for (int i = tid; i < D_*32; i += 256) {
        int c = i >> 5, gq = i & 31;
        *(float4*)&xs[c*128 + gq*4] = *(const float4*)&df[(b*D_ + c)*HW_ + pix0 + gq*4];
    }
    for (int i = tid; i < D_*E_; i += 256) {
        int e = i & 63, c = i >> 6;
        wT[c*64 + e] = w_dec[e*D_ + c];
    }
    __syncthreads();

    int ty = tid >> 5, lane = tid & 31, e0 = ty * 8;   // 4 e-pairs per thread
    ull acc[16];                                        // [ep][px]
    #pragma unroll
    for (int j = 0; j < 16; j++) acc[j] = 0ull;

    for (int c = 0; c < D_; c++) {
        float4 xv = *(const float4*)&xs[c*128 + lane*4];
        ull xd0 = dup2(xv.x), xd1 = dup2(xv.y), xd2 = dup2(xv.z), xd3 = dup2(xv.w);
        const longlong2* wr = (const longlong2*)&wT[c*64 + e0];   // 4 pairs
        longlong2 wA = wr[0], wB = wr[1];
        ull w[4] = {(ull)wA.x, (ull)wA.y, (ull)wB.x, (ull)wB.y};
        #pragma unroll
        for (int ep = 0; ep < 4; ep++) {
            fma2(acc[ep*4+0], xd0, w[ep]);
            fma2(acc[ep*4+1], xd1, w[ep]);
            fma2(acc[ep*4+2], xd2, w[ep]);
            fma2(acc[ep*4+3], xd3, w[ep]);
        }
    }
    #pragma unroll
    for (int ep = 0; ep < 4; ep++) {
        int e = e0 + 2*ep;
        float b0 = __ldg(&b_dec[e]), b1 = __ldg(&b_dec[e+1]);
        float2 u0 = unpack2(acc[ep*4+0]), u1 = unpack2(acc[ep*4+1]);
        float2 u2 = unpack2(acc[ep*4+2]), u3 = unpack2(acc[ep*4+3]);
        float4 vlo = make_float4(u0.x+b0, u1.x+b0, u2.x+b0, u3.x+b0);
        float4 vhi = make_float4(u0.y+b1, u1.y+b1, u2.y+b1, u3.y+b1);
        *(float4*)&g_q[(b*E_ + e  )*HW_ + pix0 + lane*4] = vlo;
        *(float4*)&g_q[(b*E_ + e+1)*HW_ + pix0 + lane*4] = vhi;
    }
}

// ---------------- keys + proj: two fused 64x64 GEMMs over ctx ----------------
// grid (72, K*B), block 256, dyn smem 64KB
__global__ void keysproj_kernel(const float* __restrict__ contexts,
                                const float* __restrict__ w_enc,
                                const float* __restrict__ b_enc,
                                const float* __restrict__ w_attn) {
    extern __shared__ float sm[];
    float* xs  = sm;                 // [64 c][128 pix]
    float* wkT = sm + E_*128;        // [64 c][64 e]
    float* wpT = wkT + E_*E_;
    int kb = blockIdx.y, k = kb >> 1, pix0 = blockIdx.x * 128, tid = threadIdx.x;

    for (int i = tid; i < E_*32; i += 256) {
        int c = i >> 5, gq = i & 31;
        *(float4*)&xs[c*128 + gq*4] = *(const float4*)&contexts[(kb*E_ + c)*HW_ + pix0 + gq*4];
    }
    for (int i = tid; i < E_*E_; i += 256) {
        int e = i & 63, c = i >> 6;
        wkT[c*64 + e] = w_enc[e*E_ + c];
        wpT[c*64 + e] = w_attn[e*((K_+1)*E_) + (k+1)*E_ + c];
    }
    __syncthreads();

    int ty = tid >> 5, lane = tid & 31;
    bool isp = ty >= 4;
    int e0 = (ty & 3) * 16;                 // 8 e-pairs per thread
    const float* wsrc = isp ? wpT : wkT;
    float* dst = isp ? g_proj : g_keys;

    ull acc[32];                            // [ep 8][px 4]
    #pragma unroll
    for (int j = 0; j < 32; j++) acc[j] = 0ull;

    for (int c = 0; c < E_; c++) {
        float4 xv = *(const float4*)&xs[c*128 + lane*4];
        ull xd0 = dup2(xv.x), xd1 = dup2(xv.y), xd2 = dup2(xv.z), xd3 = dup2(xv.w);
        const longlong2* wr = (const longlong2*)&wsrc[c*64 + e0];   // 8 pairs
        ull w[8];
        #pragma unroll
        for (int q = 0; q < 4; q++) { longlong2 t = wr[q]; w[q*2] = (ull)t.x; w[q*2+1] = (ull)t.y; }
        #pragma unroll
        for (int ep = 0; ep < 8; ep++) {
            fma2(acc[ep*4+0], xd0, w[ep]);
            fma2(acc[ep*4+1], xd1, w[ep]);
            fma2(acc[ep*4+2], xd2, w[ep]);
            fma2(acc[ep*4+3], xd3, w[ep]);
        }
    }
    #pragma unroll
    for (int ep = 0; ep < 8; ep++) {
        int e = e0 + 2*ep;
        float b0 = isp ? 0.f : __ldg(&b_enc[e]);
        float b1 = isp ? 0.f : __ldg(&b_enc[e+1]);
        float2 u0 = unpack2(acc[ep*4+0]), u1 = unpack2(acc[ep*4+1]);
        float2 u2 = unpack2(acc[ep*4+2]), u3 = unpack2(acc[ep*4+3]);
        float4 vlo = make_float4(u0.x+b0, u1.x+b0, u2.x+b0, u3.x+b0);
        float4 vhi = make_float4(u0.y+b1, u1.y+b1, u2.y+b1, u3.y+b1);
        *(float4*)&dst[PAD_ + (kb*E_ + e  )*HW_ + pix0 + lane*4] = vlo;
        *(float4*)&dst[PAD_ + (kb*E_ + e+1)*HW_ + pix0 + lane*4] = vhi;
    }
}

// ---------------- conv 3x3 (packed eo-pairs, D split across 2 blocks) ----------------
// grid (3, 24, B*2), block 256 (=128 pixels x 2 eo-halves), dyn smem ~53KB
#define WS_STRIDE 10   // 9 taps padded to 10 ull
__global__ void conv_kernel(const float* __restrict__ df) {
    extern __shared__ float sm[];
    float* xs = sm;                          // [16 d][6 rows][34 cols] = 3264 floats
    ull*   wsu = (ull*)(sm + 3264);          // [16 d][32 jp][10] ull pairs
    int bz = blockIdx.z;
    int b = bz >> 1, half = bz & 1;
    int w0 = blockIdx.x * 32, h0 = blockIdx.y * 4;
    int tid = threadIdx.x;
    int px = tid & 31, py = (tid >> 5) & 3, grp = tid >> 7;

    ull acc[16];                             // 16 eo-pairs = 32 eo per thread
    #pragma unroll
    for (int j = 0; j < 16; j++) acc[j] = 0ull;

    int dbase = half * 64;
    for (int d0 = dbase; d0 < dbase + 64; d0 += 16) {
        __syncthreads();
        for (int i = tid; i < 3264; i += 256) {
            int d = i / 204, r = i - d*204;
            int yy = r / 34, xx = r - yy*34;
            int gh = h0 + yy - 1, gw = w0 + xx - 1;
            float v = 0.f;
            if ((unsigned)gh < H_ && (unsigned)gw < W_)
                v = df[(b*D_ + d0 + d)*HW_ + gh*W_ + gw];
            xs[i] = v;
        }
        for (int i = tid; i < 16*32*9; i += 256) {
            int d = i / 288, r = i - d*288;
            int jp = r / 9, t = r - jp*9;
            int eo = jp * 2;
            float wlo = g_wveff[ eo   *(D_*9) + (d0 + d)*9 + t];
            float whi = g_wveff[(eo+1)*(D_*9) + (d0 + d)*9 + t];
            wsu[(d*32 + jp)*WS_STRIDE + t] = pack2(wlo, whi);
        }
        __syncthreads();

        for (int d = 0; d < 16; d++) {
            const float* xr = &xs[d*204 + py*34 + px];
            ull xp[9];
            xp[0] = dup2(xr[0]);  xp[1] = dup2(xr[1]);  xp[2] = dup2(xr[2]);
            xp[3] = dup2(xr[34]); xp[4] = dup2(xr[35]); xp[5] = dup2(xr[36]);
            xp[6] = dup2(xr[68]); xp[7] = dup2(xr[69]); xp[8] = dup2(xr[70]);
            const ull* wb = wsu + (d*32 + grp*16)*WS_STRIDE;
            #pragma unroll
            for (int jp = 0; jp < 16; jp++) {
                const ull* wp = wb + jp*WS_STRIDE;
                const longlong2* wp2 = (const longlong2*)wp;
                longlong2 wA = wp2[0], wB = wp2[1], wC = wp2[2], wD = wp2[3];
                ull w8 = wp[8];
                fma2(acc[jp], xp[0], (ull)wA.x); fma2(acc[jp], xp[1], (ull)wA.y);
                fma2(acc[jp], xp[2], (ull)wB.x); fma2(acc[jp], xp[3], (ull)wB.y);
                fma2(acc[jp], xp[4], (ull)wC.x); fma2(acc[jp], xp[5], (ull)wC.y);
                fma2(acc[jp], xp[6], (ull)wD.x); fma2(acc[jp], xp[7], (ull)wD.y);
                fma2(acc[jp], xp[8], w8);
            }
        }
    }
    int pix = (h0 + py)*W_ + w0 + px;
    float* base = g_pvh + half*(B_*E_*HW_);
    #pragma unroll
    for (int jp = 0; jp < 16; jp++) {
        int eo = (grp*16 + jp) * 2;
        float2 u = unpack2(acc[jp]);
        base[(b*E_ + eo  )*HW_ + pix] = u.x;
        base[(b*E_ + eo+1)*HW_ + pix] = u.y;
    }
}

// ---------------- attention scores + softmax ----------------
// grid 288, block 256: one thread per (k,b,pixel)
__global__ void attn_kernel(const float* __restrict__ w_agg) {
    int id = blockIdx.x * 256 + threadIdx.x;    // 73728 exact
    int kb = id / HW_;
    int pix = id - kb * HW_;
    int b = kb & 1;
    int h = pix / W_, w = pix - h*W_;

    const int off[9] = {-W_-1, -W_, -W_+1, -1, 0, 1, W_-1, W_, W_+1};
    const float* qb   = g_q    + (b*E_)*HW_ + pix;
    const float* keyb = g_keys + PAD_ + (kb*E_)*HW_ + pix;

    float s[9];
    #pragma unroll
    for (int n = 0; n < 9; n++) s[n] = 0.f;

    #pragma unroll 2
    for (int e = 0; e < E_; e++) {
        float q  = __ldg(qb + e*HW_);
        float wa = __ldg(w_agg + e);
        const float* kp = keyb + e*HW_;
        #pragma unroll
        for (int n = 0; n < 9; n++) {
            float t = tanh_hw(q + __ldg(kp + off[n]));
            s[n] = fmaf(wa, t, s[n]);
        }
    }
    // |s| <= sum|w_agg| ~ 2.6, so exp() directly is safe; invalid -> p = 0
    bool vt = h > 0, vb = h < H_-1, vl = w > 0, vr = w < W_-1;
    bool valid[9] = {vt&&vl, vt, vt&&vr, vl, true, vr, vb&&vl, vb, vb&&vr};
    float p[9], sum = 0.f;
    #pragma unroll
    for (int n = 0; n < 9; n++) {
        p[n] = valid[n] ? __expf(s[n]) : 0.f;
        sum += p[n];
    }
    float inv = 1.0f / sum;
    float* pd = g_p + (b*HW_ + pix)*36 + (kb >> 1)*9;
    #pragma unroll
    for (int n = 0; n < 9; n++) pd[n] = p[n] * inv;
}

// ---------------- output: pv halves + sum_k sum_n p * proj, bias, leaky ----------------
// grid 576, block 256 (=32 pixels x 8 eo-octets)
__global__ void out_kernel(const float* __restrict__ b_attn, float* __restrict__ out) {
    __shared__ float sp[32][37];
    int tid = threadIdx.x;
    int pixg0 = blockIdx.x * 32;
    int pl = tid & 31, ty = tid >> 5;

    for (int i = tid; i < 32*36; i += 256) {
        int a = i / 36, j = i - a*36;
        sp[a][j] = g_p[(pixg0 + a)*36 + j];
    }
    __syncthreads();

    int pg = pixg0 + pl;
    int b = pg / HW_;
    int pix = pg - b*HW_;
    int eo0 = ty * 8;
    const int off[9] = {-W_-1, -W_, -W_+1, -1, 0, 1, W_-1, W_, W_+1};

    float acc[8];
    #pragma unroll
    for (int j = 0; j < 8; j++)
        acc[j] = __ldg(&g_pvh[(b*E_ + eo0 + j)*HW_ + pix])
               + __ldg(&g_pvh[B_*E_*HW_ + (b*E_ + eo0 + j)*HW_ + pix]);

    #pragma unroll
    for (int k = 0; k < K_; k++) {
        const float* prb = g_proj + PAD_ + ((k*B_ + b)*E_ + eo0)*HW_ + pix;
        #pragma unroll
        for (int n = 0; n < 9; n++) {
            float pn = sp[pl][k*9 + n];
            int o = off[n];
            #pragma unroll
            for (int j = 0; j < 8; j++)
                acc[j] = fmaf(pn, __ldg(prb + j*HW_ + o), acc[j]);
        }
    }
    #pragma unroll
    for (int j = 0; j < 8; j++) {
        float v = acc[j] + __ldg(&g_bveff[eo0 + j]) + __ldg(&b_attn[eo0 + j]);
        v = (v >= 0.f) ? v : 0.2f * v;
        out[(b*E_ + eo0 + j)*HW_ + pix] = v;
    }
}

// ---------------- launch ----------------
extern "C" void kernel_launch(void* const* d_in, const int* in_sizes, int n_in,
                              void* d_out, int out_size) {
    const float* contexts = (const float*)d_in[0];
    const float* df       = (const float*)d_in[1];
    const float* w_enc    = (const float*)d_in[2];
    const float* b_enc    = (const float*)d_in[3];
    const float* w_dec    = (const float*)d_in[4];
    const float* b_dec    = (const float*)d_in[5];
    const float* w_agg    = (const float*)d_in[6];
    // d_in[7] = b_agg: cancels in softmax, unused
    const float* w_val    = (const float*)d_in[8];
    const float* b_val    = (const float*)d_in[9];
    const float* w_attn   = (const float*)d_in[10];
    const float* b_attn   = (const float*)d_in[11];
    float* out = (float*)d_out;

    int smq = (D_*128 + D_*E_)*4;
    int smk = (E_*128 + 2*E_*E_)*4;
    int smc = 3264*4 + 16*32*WS_STRIDE*8;
    cudaFuncSetAttribute(queries_kernel,  cudaFuncAttributeMaxDynamicSharedMemorySize, smq);
    cudaFuncSetAttribute(keysproj_kernel, cudaFuncAttributeMaxDynamicSharedMemorySize, smk);
    cudaFuncSetAttribute(conv_kernel,     cudaFuncAttributeMaxDynamicSharedMemorySize, smc);

    prep_wveff<<<288, 256>>>(w_attn, w_val);
    prep_bveff<<<1, 64>>>(w_attn, b_val);
    queries_kernel<<<dim3(HW_/128, B_), 256, smq>>>(df, w_dec, b_dec);
    keysproj_kernel<<<dim3(HW_/128, K_*B_), 256, smk>>>(contexts, w_enc, b_enc, w_attn);
    conv_kernel<<<dim3(3, 24, B_*2), 256, smc>>>(df);
    attn_kernel<<<288, 256>>>(w_agg);
    out_kernel<<<(B_*HW_)/32, 256>>>(b_attn, out);
}

// round 3
// speedup vs baseline: 1.4441x; 1.0808x over previous
#include <cuda_runtime.h>

#define E_ 64
#define D_ 128
#define K_ 4
#define B_ 2
#define H_ 96
#define W_ 96
#define HW_ (H_*W_)
#define PAD_ 128

typedef unsigned long long ull;

// ---------------- scratch (static device globals) ----------------
__device__ float g_keys[K_*B_*E_*HW_ + 2*PAD_];
__device__ float g_proj[K_*B_*E_*HW_ + 2*PAD_];
__device__ float g_q   [B_*E_*HW_];
__device__ float g_pvh [2*B_*E_*HW_];             // conv partials, 2 D-halves
__device__ float g_p   [B_*HW_*36];
__device__ float g_wveff[E_*D_*9];
__device__ float g_bveff[E_];

// ---------------- packed f32x2 helpers ----------------
__device__ __forceinline__ ull pack2(float x, float y) {
    ull r; asm("mov.b64 %0, {%1, %2};" : "=l"(r) : "f"(x), "f"(y)); return r;
}
__device__ __forceinline__ ull dup2(float x) { return pack2(x, x); }
__device__ __forceinline__ void fma2(ull& d, ull a, ull b) {
    asm("fma.rn.f32x2 %0, %1, %2, %0;" : "+l"(d) : "l"(a), "l"(b));
}
__device__ __forceinline__ float2 unpack2(ull v) {
    float2 r; asm("mov.b64 {%0, %1}, %2;" : "=f"(r.x), "=f"(r.y) : "l"(v)); return r;
}
__device__ __forceinline__ float tanh_hw(float x) {
    float r; asm("tanh.approx.f32 %0, %1;" : "=f"(r) : "f"(x)); return r;
}

// ---------------- prep: fold w_attn value-block into conv weights ----------------
__global__ void prep_wveff(const float* __restrict__ w_attn, const float* __restrict__ w_val) {
    int o = blockIdx.x * 256 + threadIdx.x;          // 73728 total, exact
    int eo = o / (D_*9);
    int r  = o - eo * (D_*9);
    const float* wa = w_attn + eo * ((K_+1)*E_);
    float a = 0.f;
    #pragma unroll 8
    for (int e = 0; e < E_; e++) a = fmaf(wa[e], w_val[e*(D_*9) + r], a);
    g_wveff[o] = a;
}

__global__ void prep_bveff(const float* __restrict__ w_attn, const float* __restrict__ b_val) {
    int eo = threadIdx.x;
    const float* wa = w_attn + eo * ((K_+1)*E_);
    float a = 0.f;
    for (int e = 0; e < E_; e++) a = fmaf(wa[e], b_val[e], a);
    g_bveff[eo] = a;
}

// ---------------- queries: g_q = w_dec @ df + b_dec ----------------
// grid (72, B), block 256: 256 px per block, 8 px x 8 e per thread
__global__ void __launch_bounds__(256) queries_kernel(
        const float* __restrict__ df,
        const float* __restrict__ w_dec,
        const float* __restrict__ b_dec) {
    extern __shared__ float sm[];
    float* xs = sm;              // [64 c][256 px]
    float* wT = sm + 64*256;     // [128 c][64 e]
    int b = blockIdx.y, pix0 = blockIdx.x * 256, tid = threadIdx.x;
    int wid = tid >> 5, lane = tid & 31;
    int e0 = wid * 8;            // 4 e-pairs

    for (int i = tid; i < D_*E_; i += 256) {
        int e = i & 63, c = i >> 6;
        wT[c*64 + e] = w_dec[e*D_ + c];
    }

    ull acc[4][8];
    #pragma unroll
    for (int ep = 0; ep < 4; ep++)
        #pragma unroll
        for (int q = 0; q < 8; q++) acc[ep][q] = 0ull;

    for (int c0 = 0; c0 < D_; c0 += 64) {
        __syncthreads();
        for (int i = tid; i < 64*64; i += 256) {
            int c = i >> 6, q = i & 63;
            *(float4*)&xs[c*256 + q*4] =
                *(const float4*)&df[(b*D_ + c0 + c)*HW_ + pix0 + q*4];
        }
        __syncthreads();

        for (int c = 0; c < 64; c++) {
            float4 xa = *(const float4*)&xs[c*256 + lane*4];
            float4 xb = *(const float4*)&xs[c*256 + 128 + lane*4];
            ull xd[8] = {dup2(xa.x), dup2(xa.y), dup2(xa.z), dup2(xa.w),
                         dup2(xb.x), dup2(xb.y), dup2(xb.z), dup2(xb.w)};
            const longlong2* wr = (const longlong2*)&wT[(c0 + c)*64 + e0];
            longlong2 wA = wr[0], wB = wr[1];
            ull w[4] = {(ull)wA.x, (ull)wA.y, (ull)wB.x, (ull)wB.y};
            #pragma unroll
            for (int ep = 0; ep < 4; ep++)
                #pragma unroll
                for (int q = 0; q < 8; q++)
                    fma2(acc[ep][q], xd[q], w[ep]);
        }
    }
    #pragma unroll
    for (int ep = 0; ep < 4; ep++) {
        int e = e0 + 2*ep;
        float b0 = __ldg(&b_dec[e]), b1 = __ldg(&b_dec[e+1]);
        float2 u[8];
        #pragma unroll
        for (int q = 0; q < 8; q++) u[q] = unpack2(acc[ep][q]);
        float4 alo = make_float4(u[0].x+b0, u[1].x+b0, u[2].x+b0, u[3].x+b0);
        float4 ahi = make_float4(u[0].y+b1, u[1].y+b1, u[2].y+b1, u[3].y+b1);
        float4 blo = make_float4(u[4].x+b0, u[5].x+b0, u[6].x+b0, u[7].x+b0);
        float4 bhi = make_float4(u[4].y+b1, u[5].y+b1, u[6].y+b1, u[7].y+b1);
        *(float4*)&g_q[(b*E_ + e  )*HW_ + pix0 + lane*4]       = alo;
        *(float4*)&g_q[(b*E_ + e+1)*HW_ + pix0 + lane*4]       = ahi;
        *(float4*)&g_q[(b*E_ + e  )*HW_ + pix0 + 128 + lane*4] = blo;
        *(float4*)&g_q[(b*E_ + e+1)*HW_ + pix0 + 128 + lane*4] = bhi;
    }
}

// ---------------- keys + proj: two fused 64x64 GEMMs over ctx ----------------
// grid (72, K*B), block 256: 256 px, warps 0-3 keys / 4-7 proj, 8 px x 16 e per thread
__global__ void __launch_bounds__(256, 1) keysproj_kernel(
        const float* __restrict__ contexts,
        const float* __restrict__ w_enc,
        const float* __restrict__ b_enc,
        const float* __restrict__ w_attn) {
    extern __shared__ float sm[];
    float* xs  = sm;                 // [64 c][256 px]
    float* wkT = sm + 64*256;        // [64 c][64 e]
    float* wpT = wkT + E_*E_;
    int kb = blockIdx.y, k = kb >> 1, pix0 = blockIdx.x * 256, tid = threadIdx.x;

    for (int i = tid; i < 64*64; i += 256) {
        int c = i >> 6, q = i & 63;
        *(float4*)&xs[c*256 + q*4] =
            *(const float4*)&contexts[(kb*E_ + c)*HW_ + pix0 + q*4];
    }
    for (int i = tid; i < E_*E_; i += 256) {
        int e = i & 63, c = i >> 6;
        wkT[c*64 + e] = w_enc[e*E_ + c];
        wpT[c*64 + e] = w_attn[e*((K_+1)*E_) + (k+1)*E_ + c];
    }
    __syncthreads();

    int wid = tid >> 5, lane = tid & 31;
    bool isp = wid >= 4;
    int e0 = (wid & 3) * 16;                 // 8 e-pairs
    const float* wsrc = isp ? wpT : wkT;
    float* dst = isp ? g_proj : g_keys;

    ull acc[8][8];
    #pragma unroll
    for (int ep = 0; ep < 8; ep++)
        #pragma unroll
        for (int q = 0; q < 8; q++) acc[ep][q] = 0ull;

    for (int c = 0; c < E_; c++) {
        float4 xa = *(const float4*)&xs[c*256 + lane*4];
        float4 xb = *(const float4*)&xs[c*256 + 128 + lane*4];
        ull xd[8] = {dup2(xa.x), dup2(xa.y), dup2(xa.z), dup2(xa.w),
                     dup2(xb.x), dup2(xb.y), dup2(xb.z), dup2(xb.w)};
        const longlong2* wr = (const longlong2*)&wsrc[c*64 + e0];
        ull w[8];
        #pragma unroll
        for (int q = 0; q < 4; q++) { longlong2 t = wr[q]; w[q*2] = (ull)t.x; w[q*2+1] = (ull)t.y; }
        #pragma unroll
        for (int ep = 0; ep < 8; ep++)
            #pragma unroll
            for (int q = 0; q < 8; q++)
                fma2(acc[ep][q], xd[q], w[ep]);
    }
    #pragma unroll
    for (int ep = 0; ep < 8; ep++) {
        int e = e0 + 2*ep;
        float b0 = isp ? 0.f : __ldg(&b_enc[e]);
        float b1 = isp ? 0.f : __ldg(&b_enc[e+1]);
        float2 u[8];
        #pragma unroll
        for (int q = 0; q < 8; q++) u[q] = unpack2(acc[ep][q]);
        float4 alo = make_float4(u[0].x+b0, u[1].x+b0, u[2].x+b0, u[3].x+b0);
        float4 ahi = make_float4(u[0].y+b1, u[1].y+b1, u[2].y+b1, u[3].y+b1);
        float4 blo = make_float4(u[4].x+b0, u[5].x+b0, u[6].x+b0, u[7].x+b0);
        float4 bhi = make_float4(u[4].y+b1, u[5].y+b1, u[6].y+b1, u[7].y+b1);
        *(float4*)&dst[PAD_ + (kb*E_ + e  )*HW_ + pix0 + lane*4]       = alo;
        *(float4*)&dst[PAD_ + (kb*E_ + e+1)*HW_ + pix0 + lane*4]       = ahi;
        *(float4*)&dst[PAD_ + (kb*E_ + e  )*HW_ + pix0 + 128 + lane*4] = blo;
        *(float4*)&dst[PAD_ + (kb*E_ + e+1)*HW_ + pix0 + 128 + lane*4] = bhi;
    }
}

// ---------------- conv 3x3 (packed eo-pairs, D split across 2 blocks) ----------------
// grid (3, 24, B*2), block 256: 8 eo-groups x 32 lanes; 4 jp-pairs x 4 px per thread
#define XROW 36
#define XD   (6*XROW)          // 216 floats per d-slice
#define WS_STRIDE 10           // 9 taps padded to 10 ull (16B alignment)
__global__ void __launch_bounds__(256) conv_kernel(const float* __restrict__ df) {
    extern __shared__ float sm[];
    float* xs = sm;                          // [16 d][6 rows][36 cols] = 3456 floats
    ull*   wsu = (ull*)(sm + 16*XD);         // [16 d][32 jp][10] ull
    int bz = blockIdx.z;
    int b = bz >> 1, half = bz & 1;
    int w0 = blockIdx.x * 32, h0 = blockIdx.y * 4;
    int tid = threadIdx.x;
    int grp = tid >> 5, lane = tid & 31;
    int jp0 = grp * 4;
    int prow = lane >> 3, pcol0 = (lane & 7) * 4;

    ull acc[4][4];
    #pragma unroll
    for (int jp = 0; jp < 4; jp++)
        #pragma unroll
        for (int j = 0; j < 4; j++) acc[jp][j] = 0ull;

    int dbase = half * 64;
    for (int d0 = dbase; d0 < dbase + 64; d0 += 16) {
        __syncthreads();
        for (int i = tid; i < 16*XD; i += 256) {
            int d = i / XD, r = i - d*XD;
            int yy = r / XROW, xx = r - yy*XROW;
            float v = 0.f;
            if (xx < 34) {
                int gh = h0 + yy - 1, gw = w0 + xx - 1;
                if ((unsigned)gh < H_ && (unsigned)gw < W_)
                    v = df[(b*D_ + d0 + d)*HW_ + gh*W_ + gw];
            }
            xs[i] = v;
        }
        for (int i = tid; i < 16*32*9; i += 256) {
            int d = i / 288, r = i - d*288;
            int jp = r / 9, t = r - jp*9;
            int eo = jp * 2;
            float wlo = g_wveff[ eo   *(D_*9) + (d0 + d)*9 + t];
            float whi = g_wveff[(eo+1)*(D_*9) + (d0 + d)*9 + t];
            wsu[(d*32 + jp)*WS_STRIDE + t] = pack2(wlo, whi);
        }
        __syncthreads();

        for (int d = 0; d < 16; d++) {
            const float* xr = &xs[d*XD + prow*XROW + pcol0];
            ull xd[3][6];
            #pragma unroll
            for (int r = 0; r < 3; r++) {
                float4 f = *(const float4*)(xr + r*XROW);
                float2 g = *(const float2*)(xr + r*XROW + 4);
                xd[r][0] = dup2(f.x); xd[r][1] = dup2(f.y); xd[r][2] = dup2(f.z);
                xd[r][3] = dup2(f.w); xd[r][4] = dup2(g.x); xd[r][5] = dup2(g.y);
            }
            const ull* wb = wsu + (d*32 + jp0)*WS_STRIDE;
            #pragma unroll
            for (int jp = 0; jp < 4; jp++) {
                const ull* wp = wb + jp*WS_STRIDE;
                const longlong2* wp2 = (const longlong2*)wp;
                longlong2 wA = wp2[0], wB = wp2[1], wC = wp2[2], wD = wp2[3];
                ull wt[9] = {(ull)wA.x, (ull)wA.y, (ull)wB.x, (ull)wB.y,
                             (ull)wC.x, (ull)wC.y, (ull)wD.x, (ull)wD.y, wp[8]};
                #pragma unroll
                for (int t = 0; t < 9; t++) {
                    int tr = t / 3, tc = t - tr*3;
                    #pragma unroll
                    for (int j = 0; j < 4; j++)
                        fma2(acc[jp][j], xd[tr][tc + j], wt[t]);
                }
            }
        }
    }
    int pix = (h0 + prow)*W_ + w0 + pcol0;
    float* base = g_pvh + half*(B_*E_*HW_);
    #pragma unroll
    for (int jp = 0; jp < 4; jp++) {
        int eo = (jp0 + jp) * 2;
        float2 u[4];
        #pragma unroll
        for (int j = 0; j < 4; j++) u[j] = unpack2(acc[jp][j]);
        float4 vlo = make_float4(u[0].x, u[1].x, u[2].x, u[3].x);
        float4 vhi = make_float4(u[0].y, u[1].y, u[2].y, u[3].y);
        *(float4*)&base[(b*E_ + eo  )*HW_ + pix] = vlo;
        *(float4*)&base[(b*E_ + eo+1)*HW_ + pix] = vhi;
    }
}

// ---------------- attention scores + softmax ----------------
// grid 288, block 256: one thread per (k,b,pixel)
__global__ void attn_kernel(const float* __restrict__ w_agg) {
    int id = blockIdx.x * 256 + threadIdx.x;    // 73728 exact
    int kb = id / HW_;
    int pix = id - kb * HW_;
    int b = kb & 1;
    int h = pix / W_, w = pix - h*W_;

    const int off[9] = {-W_-1, -W_, -W_+1, -1, 0, 1, W_-1, W_, W_+1};
    const float* qb   = g_q    + (b*E_)*HW_ + pix;
    const float* keyb = g_keys + PAD_ + (kb*E_)*HW_ + pix;

    float s[9];
    #pragma unroll
    for (int n = 0; n < 9; n++) s[n] = 0.f;

    #pragma unroll 2
    for (int e = 0; e < E_; e++) {
        float q  = __ldg(qb + e*HW_);
        float wa = __ldg(w_agg + e);
        const float* kp = keyb + e*HW_;
        #pragma unroll
        for (int n = 0; n < 9; n++) {
            float t = tanh_hw(q + __ldg(kp + off[n]));
            s[n] = fmaf(wa, t, s[n]);
        }
    }
    // |s| <= sum|w_agg| ~ 2.6, so exp() directly is safe; invalid -> p = 0
    bool vt = h > 0, vb = h < H_-1, vl = w > 0, vr = w < W_-1;
    bool valid[9] = {vt&&vl, vt, vt&&vr, vl, true, vr, vb&&vl, vb, vb&&vr};
    float p[9], sum = 0.f;
    #pragma unroll
    for (int n = 0; n < 9; n++) {
        p[n] = valid[n] ? __expf(s[n]) : 0.f;
        sum += p[n];
    }
    float inv = 1.0f / sum;
    float* pd = g_p + (b*HW_ + pix)*36 + (kb >> 1)*9;
    #pragma unroll
    for (int n = 0; n < 9; n++) pd[n] = p[n] * inv;
}

// ---------------- output: pv halves + sum_k sum_n p * proj, bias, leaky ----------------
// grid 576, block 256 (=32 pixels x 8 eo-octets)
__global__ void out_kernel(const float* __restrict__ b_attn, float* __restrict__ out) {
    __shared__ float sp[32][37];
    int tid = threadIdx.x;
    int pixg0 = blockIdx.x * 32;
    int pl = tid & 31, ty = tid >> 5;

    for (int i = tid; i < 32*36; i += 256) {
        int a = i / 36, j = i - a*36;
        sp[a][j] = g_p[(pixg0 + a)*36 + j];
    }
    __syncthreads();

    int pg = pixg0 + pl;
    int b = pg / HW_;
    int pix = pg - b*HW_;
    int eo0 = ty * 8;
    const int off[9] = {-W_-1, -W_, -W_+1, -1, 0, 1, W_-1, W_, W_+1};

    float acc[8];
    #pragma unroll
    for (int j = 0; j < 8; j++)
        acc[j] = __ldg(&g_pvh[(b*E_ + eo0 + j)*HW_ + pix])
               + __ldg(&g_pvh[B_*E_*HW_ + (b*E_ + eo0 + j)*HW_ + pix]);

    #pragma unroll
    for (int k = 0; k < K_; k++) {
        const float* prb = g_proj + PAD_ + ((k*B_ + b)*E_ + eo0)*HW_ + pix;
        #pragma unroll
        for (int n = 0; n < 9; n++) {
            float pn = sp[pl][k*9 + n];
            int o = off[n];
            #pragma unroll
            for (int j = 0; j < 8; j++)
                acc[j] = fmaf(pn, __ldg(prb + j*HW_ + o), acc[j]);
        }
    }
    #pragma unroll
    for (int j = 0; j < 8; j++) {
        float v = acc[j] + __ldg(&g_bveff[eo0 + j]) + __ldg(&b_attn[eo0 + j]);
        v = (v >= 0.f) ? v : 0.2f * v;
        out[(b*E_ + eo0 + j)*HW_ + pix] = v;
    }
}

// ---------------- launch ----------------
extern "C" void kernel_launch(void* const* d_in, const int* in_sizes, int n_in,
                              void* d_out, int out_size) {
    const float* contexts = (const float*)d_in[0];
    const float* df       = (const float*)d_in[1];
    const float* w_enc    = (const float*)d_in[2];
    const float* b_enc    = (const float*)d_in[3];
    const float* w_dec    = (const float*)d_in[4];
    const float* b_dec    = (const float*)d_in[5];
    const float* w_agg    = (const float*)d_in[6];
    // d_in[7] = b_agg: cancels in softmax, unused
    const float* w_val    = (const float*)d_in[8];
    const float* b_val    = (const float*)d_in[9];
    const float* w_attn   = (const float*)d_in[10];
    const float* b_attn   = (const float*)d_in[11];
    float* out = (float*)d_out;

    int smq = (64*256 + D_*E_)*4;            // 96 KB
    int smk = (64*256 + 2*E_*E_)*4;          // 96 KB
    int smc = 16*XD*4 + 16*32*WS_STRIDE*8;   // ~54 KB
    cudaFuncSetAttribute(queries_kernel,  cudaFuncAttributeMaxDynamicSharedMemorySize, smq);
    cudaFuncSetAttribute(keysproj_kernel, cudaFuncAttributeMaxDynamicSharedMemorySize, smk);
    cudaFuncSetAttribute(conv_kernel,     cudaFuncAttributeMaxDynamicSharedMemorySize, smc);

    prep_wveff<<<288, 256>>>(w_attn, w_val);
    prep_bveff<<<1, 64>>>(w_attn, b_val);
    queries_kernel<<<dim3(HW_/256, B_), 256, smq>>>(df, w_dec, b_dec);
    keysproj_kernel<<<dim3(HW_/256, K_*B_), 256, smk>>>(contexts, w_enc, b_enc, w_attn);
    conv_kernel<<<dim3(3, 24, B_*2), 256, smc>>>(df);
    attn_kernel<<<288, 256>>>(w_agg);
    out_kernel<<<(B_*HW_)/32, 256>>>(b_attn, out);
}

// round 5
// speedup vs baseline: 1.5039x; 1.0414x over previous
#include <cuda_runtime.h>
#include <cuda_bf16.h>
#include <cstdint>

#define E_ 64
#define D_ 128
#define K_ 4
#define B_ 2
#define H_ 96
#define W_ 96
#define HW_ (H_*W_)
#define PAD_ 128

typedef unsigned long long ull;

// ---------------- scratch (static device globals) ----------------
__device__ float g_keys[K_*B_*E_*HW_ + 2*PAD_];
__device__ float g_proj[K_*B_*E_*HW_ + 2*PAD_];
__device__ float g_q   [B_*E_*HW_];
__device__ float g_pvh [2*B_*E_*HW_];             // conv partials, 2 D-halves
__device__ float g_p   [B_*HW_*36];
__device__ float g_wveff[E_*D_*9];
__device__ float g_bveff[E_];

// ---------------- packed f32x2 / misc helpers ----------------
__device__ __forceinline__ ull pack2(float x, float y) {
    ull r; asm("mov.b64 %0, {%1, %2};" : "=l"(r) : "f"(x), "f"(y)); return r;
}
__device__ __forceinline__ ull dup2(float x) { return pack2(x, x); }
__device__ __forceinline__ void fma2(ull& d, ull a, ull b) {
    asm("fma.rn.f32x2 %0, %1, %2, %0;" : "+l"(d) : "l"(a), "l"(b));
}
__device__ __forceinline__ float2 unpack2(ull v) {
    float2 r; asm("mov.b64 {%0, %1}, %2;" : "=f"(r.x), "=f"(r.y) : "l"(v)); return r;
}
__device__ __forceinline__ float tanh_hw(float x) {
    float r; asm("tanh.approx.f32 %0, %1;" : "=f"(r) : "f"(x)); return r;
}
__device__ __forceinline__ unsigned bfpack2(float a, float b) {
    __nv_bfloat162 t = __floats2bfloat162_rn(a, b);
    return *(unsigned*)&t;
}
__device__ __forceinline__ void mma16816(float* d, const uint32_t* a,
                                         uint32_t b0, uint32_t b1) {
    asm volatile(
        "mma.sync.aligned.m16n8k16.row.col.f32.bf16.bf16.f32 "
        "{%0,%1,%2,%3}, {%4,%5,%6,%7}, {%8,%9}, {%0,%1,%2,%3};"
        : "+f"(d[0]), "+f"(d[1]), "+f"(d[2]), "+f"(d[3])
        : "r"(a[0]), "r"(a[1]), "r"(a[2]), "r"(a[3]), "r"(b0), "r"(b1));
}

// ---------------- prep: fold w_attn value-block into conv weights ----------------
__global__ void prep_wveff(const float* __restrict__ w_attn, const float* __restrict__ w_val) {
    int o = blockIdx.x * 256 + threadIdx.x;          // 73728 total, exact
    int eo = o / (D_*9);
    int r  = o - eo * (D_*9);
    const float* wa = w_attn + eo * ((K_+1)*E_);
    float a = 0.f;
    #pragma unroll 8
    for (int e = 0; e < E_; e++) a = fmaf(wa[e], w_val[e*(D_*9) + r], a);
    g_wveff[o] = a;
}

__global__ void prep_bveff(const float* __restrict__ w_attn, const float* __restrict__ b_val) {
    int eo = threadIdx.x;
    const float* wa = w_attn + eo * ((K_+1)*E_);
    float a = 0.f;
    for (int e = 0; e < E_; e++) a = fmaf(wa[e], b_val[e], a);
    g_bveff[eo] = a;
}

// ---------------- queries: g_q = w_dec @ df + b_dec (scalar) ----------------
__global__ void __launch_bounds__(256) queries_kernel(
        const float* __restrict__ df,
        const float* __restrict__ w_dec,
        const float* __restrict__ b_dec) {
    extern __shared__ float sm[];
    float* xs = sm;              // [64 c][256 px]
    float* wT = sm + 64*256;     // [128 c][64 e]
    int b = blockIdx.y, pix0 = blockIdx.x * 256, tid = threadIdx.x;
    int wid = tid >> 5, lane = tid & 31;
    int e0 = wid * 8;

    for (int i = tid; i < D_*E_; i += 256) {
        int e = i & 63, c = i >> 6;
        wT[c*64 + e] = w_dec[e*D_ + c];
    }

    ull acc[4][8];
    #pragma unroll
    for (int ep = 0; ep < 4; ep++)
        #pragma unroll
        for (int q = 0; q < 8; q++) acc[ep][q] = 0ull;

    for (int c0 = 0; c0 < D_; c0 += 64) {
        __syncthreads();
        for (int i = tid; i < 64*64; i += 256) {
            int c = i >> 6, q = i & 63;
            *(float4*)&xs[c*256 + q*4] =
                *(const float4*)&df[(b*D_ + c0 + c)*HW_ + pix0 + q*4];
        }
        __syncthreads();

        for (int c = 0; c < 64; c++) {
            float4 xa = *(const float4*)&xs[c*256 + lane*4];
            float4 xb = *(const float4*)&xs[c*256 + 128 + lane*4];
            ull xd[8] = {dup2(xa.x), dup2(xa.y), dup2(xa.z), dup2(xa.w),
                         dup2(xb.x), dup2(xb.y), dup2(xb.z), dup2(xb.w)};
            const longlong2* wr = (const longlong2*)&wT[(c0 + c)*64 + e0];
            longlong2 wA = wr[0], wB = wr[1];
            ull w[4] = {(ull)wA.x, (ull)wA.y, (ull)wB.x, (ull)wB.y};
            #pragma unroll
            for (int ep = 0; ep < 4; ep++)
                #pragma unroll
                for (int q = 0; q < 8; q++)
                    fma2(acc[ep][q], xd[q], w[ep]);
        }
    }
    #pragma unroll
    for (int ep = 0; ep < 4; ep++) {
        int e = e0 + 2*ep;
        float b0 = __ldg(&b_dec[e]), b1 = __ldg(&b_dec[e+1]);
        float2 u[8];
        #pragma unroll
        for (int q = 0; q < 8; q++) u[q] = unpack2(acc[ep][q]);
        float4 alo = make_float4(u[0].x+b0, u[1].x+b0, u[2].x+b0, u[3].x+b0);
        float4 ahi = make_float4(u[0].y+b1, u[1].y+b1, u[2].y+b1, u[3].y+b1);
        float4 blo = make_float4(u[4].x+b0, u[5].x+b0, u[6].x+b0, u[7].x+b0);
        float4 bhi = make_float4(u[4].y+b1, u[5].y+b1, u[6].y+b1, u[7].y+b1);
        *(float4*)&g_q[(b*E_ + e  )*HW_ + pix0 + lane*4]       = alo;
        *(float4*)&g_q[(b*E_ + e+1)*HW_ + pix0 + lane*4]       = ahi;
        *(float4*)&g_q[(b*E_ + e  )*HW_ + pix0 + 128 + lane*4] = blo;
        *(float4*)&g_q[(b*E_ + e+1)*HW_ + pix0 + 128 + lane*4] = bhi;
    }
}

// ---------------- keys + proj via mma.sync bf16 3-term split ----------------
// D[128 m][256 px] = Wstack[128,64] @ X[64,256]; rows 0-63 keys, 64-127 proj.
// grid (36, K*B), block 256 (8 warps x m16 slabs). smem b32 layout, row stride 33.
#define KP_AH 0
#define KP_AL 4224           // 128*33
#define KP_BH 8448
#define KP_BL 16896          // + 256*33
#define KP_TOT32 25344       // *4 = 101376 bytes

__global__ void __launch_bounds__(256) keysproj_mma(
        const float* __restrict__ contexts,
        const float* __restrict__ w_enc,
        const float* __restrict__ b_enc,
        const float* __restrict__ w_attn) {
    extern __shared__ uint32_t sm32[];
    uint32_t* AH = sm32 + KP_AH;
    uint32_t* AL = sm32 + KP_AL;
    uint32_t* BH = sm32 + KP_BH;
    uint32_t* BL = sm32 + KP_BL;
    int tid = threadIdx.x, wid = tid >> 5, lane = tid & 31;
    int kb = blockIdx.y, k = kb >> 1;
    int pix0 = blockIdx.x * 256;

    // A fill: 128 m-rows x 32 c-pairs
    for (int i = tid; i < 128*32; i += 256) {
        int m = i >> 5, c2 = i & 31;
        const float* row = (m < 64) ? (w_enc + m*64)
                                    : (w_attn + (m - 64)*((K_+1)*E_) + (k + 1)*E_);
        float v0 = row[2*c2], v1 = row[2*c2 + 1];
        float h0 = __bfloat162float(__float2bfloat16(v0));
        float h1 = __bfloat162float(__float2bfloat16(v1));
        AH[m*33 + c2] = bfpack2(v0, v1);
        AL[m*33 + c2] = bfpack2(v0 - h0, v1 - h1);
    }
    // B fill: 256 px-rows x 32 c-pairs (transpose from [c][px])
    const float* ctx = contexts + (size_t)kb * E_ * HW_ + pix0;
    for (int i = tid; i < 256*32; i += 256) {
        int c2 = i >> 8, px = i & 255;
        float v0 = __ldg(ctx + (2*c2)*HW_ + px);
        float v1 = __ldg(ctx + (2*c2 + 1)*HW_ + px);
        float h0 = __bfloat162float(__float2bfloat16(v0));
        float h1 = __bfloat162float(__float2bfloat16(v1));
        BH[px*33 + c2] = bfpack2(v0, v1);
        BL[px*33 + c2] = bfpack2(v0 - h0, v1 - h1);
    }
    __syncthreads();

    int g = lane >> 2, tig = lane & 3;
    int m0 = wid * 16;
    int row0 = m0 + g, row1 = m0 + g + 8;

    // preload A fragments for all 4 k-tiles (hi + lo)
    uint32_t ah[4][4], al[4][4];
    #pragma unroll
    for (int kt = 0; kt < 4; kt++) {
        int base = kt*8 + tig;
        ah[kt][0] = AH[row0*33 + base];     ah[kt][1] = AH[row1*33 + base];
        ah[kt][2] = AH[row0*33 + base + 4]; ah[kt][3] = AH[row1*33 + base + 4];
        al[kt][0] = AL[row0*33 + base];     al[kt][1] = AL[row1*33 + base];
        al[kt][2] = AL[row0*33 + base + 4]; al[kt][3] = AL[row1*33 + base + 4];
    }

    float bias0 = (row0 < 64) ? __ldg(&b_enc[row0]) : 0.f;
    float bias1 = (row1 < 64) ? __ldg(&b_enc[row1]) : 0.f;
    float* dst0 = (row0 < 64)
        ? (g_keys + PAD_ + (size_t)(kb*E_ + row0)*HW_ + pix0)
        : (g_proj + PAD_ + (size_t)(kb*E_ + row0 - 64)*HW_ + pix0);
    float* dst1 = (row1 < 64)
        ? (g_keys + PAD_ + (size_t)(kb*E_ + row1)*HW_ + pix0)
        : (g_proj + PAD_ + (size_t)(kb*E_ + row1 - 64)*HW_ + pix0);

    #pragma unroll 4
    for (int nt = 0; nt < 32; nt++) {
        int n0 = nt*8;
        float d[4] = {0.f, 0.f, 0.f, 0.f};
        #pragma unroll
        for (int kt = 0; kt < 4; kt++) {
            int bb = (n0 + g)*33 + kt*8 + tig;
            uint32_t b0h = BH[bb], b1h = BH[bb + 4];
            uint32_t b0l = BL[bb], b1l = BL[bb + 4];
            mma16816(d, ah[kt], b0h, b1h);
            mma16816(d, al[kt], b0h, b1h);
            mma16816(d, ah[kt], b0l, b1l);
        }
        int col = n0 + 2*tig;
        *(float2*)&dst0[col] = make_float2(d[0] + bias0, d[1] + bias0);
        *(float2*)&dst1[col] = make_float2(d[2] + bias1, d[3] + bias1);
    }
}

// ---------------- conv 3x3 (packed eo-pairs, D split across 2 blocks) ----------------
#define XROW 36
#define XD   (6*XROW)
#define WS_STRIDE 10
__global__ void __launch_bounds__(256) conv_kernel(const float* __restrict__ df) {
    extern __shared__ float sm[];
    float* xs = sm;                          // [16 d][6 rows][36 cols]
    ull*   wsu = (ull*)(sm + 16*XD);         // [16 d][32 jp][10] ull
    int bz = blockIdx.z;
    int b = bz >> 1, half = bz & 1;
    int w0 = blockIdx.x * 32, h0 = blockIdx.y * 4;
    int tid = threadIdx.x;
    int grp = tid >> 5, lane = tid & 31;
    int jp0 = grp * 4;
    int prow = lane >> 3, pcol0 = (lane & 7) * 4;

    ull acc[4][4];
    #pragma unroll
    for (int jp = 0; jp < 4; jp++)
        #pragma unroll
        for (int j = 0; j < 4; j++) acc[jp][j] = 0ull;

    int dbase = half * 64;
    for (int d0 = dbase; d0 < dbase + 64; d0 += 16) {
        __syncthreads();
        for (int i = tid; i < 16*XD; i += 256) {
            int d = i / XD, r = i - d*XD;
            int yy = r / XROW, xx = r - yy*XROW;
            float v = 0.f;
            if (xx < 34) {
                int gh = h0 + yy - 1, gw = w0 + xx - 1;
                if ((unsigned)gh < H_ && (unsigned)gw < W_)
                    v = df[(b*D_ + d0 + d)*HW_ + gh*W_ + gw];
            }
            xs[i] = v;
        }
        for (int i = tid; i < 16*32*9; i += 256) {
            int d = i / 288, r = i - d*288;
            int jp = r / 9, t = r - jp*9;
            int eo = jp * 2;
            float wlo = g_wveff[ eo   *(D_*9) + (d0 + d)*9 + t];
            float whi = g_wveff[(eo+1)*(D_*9) + (d0 + d)*9 + t];
            wsu[(d*32 + jp)*WS_STRIDE + t] = pack2(wlo, whi);
        }
        __syncthreads();

        for (int d = 0; d < 16; d++) {
            const float* xr = &xs[d*XD + prow*XROW + pcol0];
            ull xd[3][6];
            #pragma unroll
            for (int r = 0; r < 3; r++) {
                float4 f = *(const float4*)(xr + r*XROW);
                float2 g2 = *(const float2*)(xr + r*XROW + 4);
                xd[r][0] = dup2(f.x); xd[r][1] = dup2(f.y); xd[r][2] = dup2(f.z);
                xd[r][3] = dup2(f.w); xd[r][4] = dup2(g2.x); xd[r][5] = dup2(g2.y);
            }
            const ull* wb = wsu + (d*32 + jp0)*WS_STRIDE;
            #pragma unroll
            for (int jp = 0; jp < 4; jp++) {
                const ull* wp = wb + jp*WS_STRIDE;
                const longlong2* wp2 = (const longlong2*)wp;
                longlong2 wA = wp2[0], wB = wp2[1], wC = wp2[2], wD = wp2[3];
                ull wt[9] = {(ull)wA.x, (ull)wA.y, (ull)wB.x, (ull)wB.y,
                             (ull)wC.x, (ull)wC.y, (ull)wD.x, (ull)wD.y, wp[8]};
                #pragma unroll
                for (int t = 0; t < 9; t++) {
                    int tr = t / 3, tc = t - tr*3;
                    #pragma unroll
                    for (int j = 0; j < 4; j++)
                        fma2(acc[jp][j], xd[tr][tc + j], wt[t]);
                }
            }
        }
    }
    int pix = (h0 + prow)*W_ + w0 + pcol0;
    float* base = g_pvh + half*(B_*E_*HW_);
    #pragma unroll
    for (int jp = 0; jp < 4; jp++) {
        int eo = (jp0 + jp) * 2;
        float2 u[4];
        #pragma unroll
        for (int j = 0; j < 4; j++) u[j] = unpack2(acc[jp][j]);
        float4 vlo = make_float4(u[0].x, u[1].x, u[2].x, u[3].x);
        float4 vhi = make_float4(u[0].y, u[1].y, u[2].y, u[3].y);
        *(float4*)&base[(b*E_ + eo  )*HW_ + pix] = vlo;
        *(float4*)&base[(b*E_ + eo+1)*HW_ + pix] = vhi;
    }
}

// ---------------- attention scores + softmax ----------------
__global__ void attn_kernel(const float* __restrict__ w_agg) {
    int id = blockIdx.x * 256 + threadIdx.x;    // 73728 exact
    int kb = id / HW_;
    int pix = id - kb * HW_;
    int b = kb & 1;
    int h = pix / W_, w = pix - h*W_;

    const int off[9] = {-W_-1, -W_, -W_+1, -1, 0, 1, W_-1, W_, W_+1};
    const float* qb   = g_q    + (b*E_)*HW_ + pix;
    const float* keyb = g_keys + PAD_ + (kb*E_)*HW_ + pix;

    float s[9];
    #pragma unroll
    for (int n = 0; n < 9; n++) s[n] = 0.f;

    #pragma unroll 2
    for (int e = 0; e < E_; e++) {
        float q  = __ldg(qb + e*HW_);
        float wa = __ldg(w_agg + e);
        const float* kp = keyb + e*HW_;
        #pragma unroll
        for (int n = 0; n < 9; n++) {
            float t = tanh_hw(q + __ldg(kp + off[n]));
            s[n] = fmaf(wa, t, s[n]);
        }
    }
    bool vt = h > 0, vb = h < H_-1, vl = w > 0, vr = w < W_-1;
    bool valid[9] = {vt&&vl, vt, vt&&vr, vl, true, vr, vb&&vl, vb, vb&&vr};
    float p[9], sum = 0.f;
    #pragma unroll
    for (int n = 0; n < 9; n++) {
        p[n] = valid[n] ? __expf(s[n]) : 0.f;
        sum += p[n];
    }
    float inv = 1.0f / sum;
    float* pd = g_p + (b*HW_ + pix)*36 + (kb >> 1)*9;
    #pragma unroll
    for (int n = 0; n < 9; n++) pd[n] = p[n] * inv;
}

// ---------------- output: pv halves + sum_k sum_n p * proj, bias, leaky ----------------
__global__ void out_kernel(const float* __restrict__ b_attn, float* __restrict__ out) {
    __shared__ float sp[32][37];
    int tid = threadIdx.x;
    int pixg0 = blockIdx.x * 32;
    int pl = tid & 31, ty = tid >> 5;

    for (int i = tid; i < 32*36; i += 256) {
        int a = i / 36, j = i - a*36;
        sp[a][j] = g_p[(pixg0 + a)*36 + j];
    }
    __syncthreads();

    int pg = pixg0 + pl;
    int b = pg / HW_;
    int pix = pg - b*HW_;
    int eo0 = ty * 8;
    const int off[9] = {-W_-1, -W_, -W_+1, -1, 0, 1, W_-1, W_, W_+1};

    float acc[8];
    #pragma unroll
    for (int j = 0; j < 8; j++)
        acc[j] = __ldg(&g_pvh[(b*E_ + eo0 + j)*HW_ + pix])
               + __ldg(&g_pvh[B_*E_*HW_ + (b*E_ + eo0 + j)*HW_ + pix]);

    #pragma unroll
    for (int k = 0; k < K_; k++) {
        const float* prb = g_proj + PAD_ + ((k*B_ + b)*E_ + eo0)*HW_ + pix;
        #pragma unroll
        for (int n = 0; n < 9; n++) {
            float pn = sp[pl][k*9 + n];
            int o = off[n];
            #pragma unroll
            for (int j = 0; j < 8; j++)
                acc[j] = fmaf(pn, __ldg(prb + j*HW_ + o), acc[j]);
        }
    }
    #pragma unroll
    for (int j = 0; j < 8; j++) {
        float v = acc[j] + __ldg(&g_bveff[eo0 + j]) + __ldg(&b_attn[eo0 + j]);
        v = (v >= 0.f) ? v : 0.2f * v;
        out[(b*E_ + eo0 + j)*HW_ + pix] = v;
    }
}

// ---------------- launch ----------------
extern "C" void kernel_launch(void* const* d_in, const int* in_sizes, int n_in,
                              void* d_out, int out_size) {
    const float* contexts = (const float*)d_in[0];
    const float* df       = (const float*)d_in[1];
    const float* w_enc    = (const float*)d_in[2];
    const float* b_enc    = (const float*)d_in[3];
    const float* w_dec    = (const float*)d_in[4];
    const float* b_dec    = (const float*)d_in[5];
    const float* w_agg    = (const float*)d_in[6];
    // d_in[7] = b_agg: cancels in softmax, unused
    const float* w_val    = (const float*)d_in[8];
    const float* b_val    = (const float*)d_in[9];
    const float* w_attn   = (const float*)d_in[10];
    const float* b_attn   = (const float*)d_in[11];
    float* out = (float*)d_out;

    int smq = (64*256 + D_*E_)*4;            // 96 KB
    int smk = KP_TOT32 * 4;                  // ~99 KB
    int smc = 16*XD*4 + 16*32*WS_STRIDE*8;   // ~54 KB
    cudaFuncSetAttribute(queries_kernel,  cudaFuncAttributeMaxDynamicSharedMemorySize, smq);
    cudaFuncSetAttribute(keysproj_mma,    cudaFuncAttributeMaxDynamicSharedMemorySize, smk);
    cudaFuncSetAttribute(conv_kernel,     cudaFuncAttributeMaxDynamicSharedMemorySize, smc);

    prep_wveff<<<288, 256>>>(w_attn, w_val);
    prep_bveff<<<1, 64>>>(w_attn, b_val);
    queries_kernel<<<dim3(HW_/256, B_), 256, smq>>>(df, w_dec, b_dec);
    keysproj_mma<<<dim3(HW_/256, K_*B_), 256, smk>>>(contexts, w_enc, b_enc, w_attn);
    conv_kernel<<<dim3(3, 24, B_*2), 256, smc>>>(df);
    attn_kernel<<<288, 256>>>(w_agg);
    out_kernel<<<(B_*HW_)/32, 256>>>(b_attn, out);
}

// round 6
// speedup vs baseline: 1.7023x; 1.1319x over previous
#include <cuda_runtime.h>
#include <cuda_bf16.h>
#include <cstdint>

#define E_ 64
#define D_ 128
#define K_ 4
#define B_ 2
#define H_ 96
#define W_ 96
#define HW_ (H_*W_)
#define PAD_ 128

typedef unsigned long long ull;

// ---------------- scratch (static device globals) ----------------
__device__ float g_keys[K_*B_*E_*HW_ + 2*PAD_];
__device__ float g_proj[K_*B_*E_*HW_ + 2*PAD_];
__device__ float g_q   [B_*E_*HW_];
__device__ float g_pvh [2*B_*E_*HW_];             // conv partials, 2 D-halves
__device__ float g_p   [B_*HW_*36];
__device__ float g_wveff[E_*D_*9];
__device__ float g_bveff[E_];

// ---------------- helpers ----------------
__device__ __forceinline__ ull pack2(float x, float y) {
    ull r; asm("mov.b64 %0, {%1, %2};" : "=l"(r) : "f"(x), "f"(y)); return r;
}
__device__ __forceinline__ ull dup2(float x) { return pack2(x, x); }
__device__ __forceinline__ void fma2(ull& d, ull a, ull b) {
    asm("fma.rn.f32x2 %0, %1, %2, %0;" : "+l"(d) : "l"(a), "l"(b));
}
__device__ __forceinline__ float2 unpack2(ull v) {
    float2 r; asm("mov.b64 {%0, %1}, %2;" : "=f"(r.x), "=f"(r.y) : "l"(v)); return r;
}
__device__ __forceinline__ float tanh_hw(float x) {
    float r; asm("tanh.approx.f32 %0, %1;" : "=f"(r) : "f"(x)); return r;
}
__device__ __forceinline__ unsigned bfpack2(float a, float b) {
    __nv_bfloat162 t = __floats2bfloat162_rn(a, b);
    return *(unsigned*)&t;
}
__device__ __forceinline__ void mma16816(float* d, const uint32_t* a,
                                         uint32_t b0, uint32_t b1) {
    asm volatile(
        "mma.sync.aligned.m16n8k16.row.col.f32.bf16.bf16.f32 "
        "{%0,%1,%2,%3}, {%4,%5,%6,%7}, {%8,%9}, {%0,%1,%2,%3};"
        : "+f"(d[0]), "+f"(d[1]), "+f"(d[2]), "+f"(d[3])
        : "r"(a[0]), "r"(a[1]), "r"(a[2]), "r"(a[3]), "r"(b0), "r"(b1));
}
__device__ __forceinline__ void ldmat4(uint32_t& a, uint32_t& b, uint32_t& c,
                                       uint32_t& d, uint32_t saddr) {
    asm volatile("ldmatrix.sync.aligned.m8n8.x4.shared.b16 {%0,%1,%2,%3}, [%4];"
                 : "=r"(a), "=r"(b), "=r"(c), "=r"(d) : "r"(saddr));
}
__device__ __forceinline__ uint32_t smem_u32(const void* p) {
    uint32_t a;
    asm("{ .reg .u64 t; cvta.to.shared.u64 t, %1; cvt.u32.u64 %0, t; }" : "=r"(a) : "l"(p));
    return a;
}

// ---------------- prep: fold w_attn value-block into conv weights ----------------
__global__ void prep_wveff(const float* __restrict__ w_attn, const float* __restrict__ w_val) {
    int o = blockIdx.x * 256 + threadIdx.x;          // 73728 total, exact
    int eo = o / (D_*9);
    int r  = o - eo * (D_*9);
    const float* wa = w_attn + eo * ((K_+1)*E_);
    float a = 0.f;
    #pragma unroll 8
    for (int e = 0; e < E_; e++) a = fmaf(wa[e], w_val[e*(D_*9) + r], a);
    g_wveff[o] = a;
}

__global__ void prep_bveff(const float* __restrict__ w_attn, const float* __restrict__ b_val) {
    int eo = threadIdx.x;
    const float* wa = w_attn + eo * ((K_+1)*E_);
    float a = 0.f;
    for (int e = 0; e < E_; e++) a = fmaf(wa[e], b_val[e], a);
    g_bveff[eo] = a;
}

// ---------------- queries via mma.sync bf16 3-term split ----------------
// D[64 m][128 px] = w_dec[64,128] @ df[128,128px]. grid (72, B), block 256.
// 8 warps = 4 m-slabs x 2 n-halves. smem row stride 68 (16B-aligned, conflict-free).
#define QA_H 0
#define QA_L 4352            // 64*68
#define QB_H 8704
#define QB_L 17408           // + 128*68
#define Q_TOT32 26112        // *4 = 104448 bytes

__global__ void __launch_bounds__(256) queries_mma(
        const float* __restrict__ df,
        const float* __restrict__ w_dec,
        const float* __restrict__ b_dec) {
    extern __shared__ uint32_t sm32[];
    uint32_t* AH = sm32 + QA_H;
    uint32_t* AL = sm32 + QA_L;
    uint32_t* BH = sm32 + QB_H;
    uint32_t* BL = sm32 + QB_L;
    uint32_t sb = smem_u32(sm32);
    int tid = threadIdx.x, wid = tid >> 5, lane = tid & 31;
    int b = blockIdx.y, pix0 = blockIdx.x * 128;

    // A fill: 64 m-rows x 64 c-pairs
    for (int i = tid; i < 64*64; i += 256) {
        int m = i >> 6, c2 = i & 63;
        float v0 = w_dec[m*D_ + 2*c2], v1 = w_dec[m*D_ + 2*c2 + 1];
        float h0 = __bfloat162float(__float2bfloat16(v0));
        float h1 = __bfloat162float(__float2bfloat16(v1));
        AH[m*68 + c2] = bfpack2(v0, v1);
        AL[m*68 + c2] = bfpack2(v0 - h0, v1 - h1);
    }
    // B fill: 128 px-rows x 64 c-pairs
    const float* dfb = df + (size_t)b * D_ * HW_ + pix0;
    for (int i = tid; i < 128*64; i += 256) {
        int c2 = i >> 7, px = i & 127;
        float v0 = __ldg(dfb + (2*c2)*HW_ + px);
        float v1 = __ldg(dfb + (2*c2 + 1)*HW_ + px);
        float h0 = __bfloat162float(__float2bfloat16(v0));
        float h1 = __bfloat162float(__float2bfloat16(v1));
        BH[px*68 + c2] = bfpack2(v0, v1);
        BL[px*68 + c2] = bfpack2(v0 - h0, v1 - h1);
    }
    __syncthreads();

    int g = lane >> 2, tig = lane & 3;
    int mslab = wid & 3, nhalf = wid >> 2;
    int row0 = mslab*16 + g, row1 = row0 + 8;

    uint32_t ah[8][4], al[8][4];
    #pragma unroll
    for (int kt = 0; kt < 8; kt++) {
        int base = kt*8 + tig;
        ah[kt][0] = AH[row0*68 + base];     ah[kt][1] = AH[row1*68 + base];
        ah[kt][2] = AH[row0*68 + base + 4]; ah[kt][3] = AH[row1*68 + base + 4];
        al[kt][0] = AL[row0*68 + base];     al[kt][1] = AL[row1*68 + base];
        al[kt][2] = AL[row0*68 + base + 4]; al[kt][3] = AL[row1*68 + base + 4];
    }

    int m8 = lane >> 3, r8 = lane & 7;
    uint32_t colb = ((m8 >> 1) << 3) + ((m8 & 1) << 2);
    uint32_t bhA0 = sb + (QB_H + r8*68 + colb)*4 + nhalf*8*2176;
    uint32_t blA0 = sb + (QB_L + r8*68 + colb)*4 + nhalf*8*2176;

    float bias0 = __ldg(&b_dec[row0]);
    float bias1 = __ldg(&b_dec[row1]);
    float* dst0 = g_q + (size_t)(b*E_ + row0)*HW_ + pix0;
    float* dst1 = g_q + (size_t)(b*E_ + row1)*HW_ + pix0;

    #pragma unroll
    for (int nt = 0; nt < 8; nt++) {
        uint32_t bh[16], bl[16];
        uint32_t aB = bhA0 + nt*2176;           // 8*68*4 bytes per nt
        uint32_t aL = blA0 + nt*2176;
        ldmat4(bh[0], bh[1], bh[2], bh[3], aB);         // kt 0,1
        ldmat4(bh[4], bh[5], bh[6], bh[7], aB + 64);    // kt 2,3
        ldmat4(bh[8], bh[9], bh[10], bh[11], aB + 128); // kt 4,5
        ldmat4(bh[12], bh[13], bh[14], bh[15], aB + 192);
        ldmat4(bl[0], bl[1], bl[2], bl[3], aL);
        ldmat4(bl[4], bl[5], bl[6], bl[7], aL + 64);
        ldmat4(bl[8], bl[9], bl[10], bl[11], aL + 128);
        ldmat4(bl[12], bl[13], bl[14], bl[15], aL + 192);

        float d[4] = {0.f, 0.f, 0.f, 0.f};
        #pragma unroll
        for (int kt = 0; kt < 8; kt++) {
            mma16816(d, ah[kt], bh[2*kt], bh[2*kt+1]);
            mma16816(d, al[kt], bh[2*kt], bh[2*kt+1]);
            mma16816(d, ah[kt], bl[2*kt], bl[2*kt+1]);
        }
        int col = (nhalf*8 + nt)*8 + 2*tig;
        *(float2*)&dst0[col] = make_float2(d[0] + bias0, d[1] + bias0);
        *(float2*)&dst1[col] = make_float2(d[2] + bias1, d[3] + bias1);
    }
}

// ---------------- keys + proj via mma.sync bf16 3-term split + ldmatrix ----------------
// D[128 m][256 px]; rows 0-63 keys, 64-127 proj. grid (36, K*B), block 256.
#define KP_AH 0
#define KP_AL 4608           // 128*36
#define KP_BH 9216
#define KP_BL 18432          // + 256*36
#define KP_TOT32 27648       // *4 = 110592 bytes

__global__ void __launch_bounds__(256) keysproj_mma(
        const float* __restrict__ contexts,
        const float* __restrict__ w_enc,
        const float* __restrict__ b_enc,
        const float* __restrict__ w_attn) {
    extern __shared__ uint32_t sm32[];
    uint32_t* AH = sm32 + KP_AH;
    uint32_t* AL = sm32 + KP_AL;
    uint32_t* BH = sm32 + KP_BH;
    uint32_t* BL = sm32 + KP_BL;
    uint32_t sb = smem_u32(sm32);
    int tid = threadIdx.x, wid = tid >> 5, lane = tid & 31;
    int kb = blockIdx.y, k = kb >> 1;
    int pix0 = blockIdx.x * 256;

    // A fill: 128 m-rows x 32 c-pairs
    for (int i = tid; i < 128*32; i += 256) {
        int m = i >> 5, c2 = i & 31;
        const float* row = (m < 64) ? (w_enc + m*64)
                                    : (w_attn + (m - 64)*((K_+1)*E_) + (k + 1)*E_);
        float v0 = row[2*c2], v1 = row[2*c2 + 1];
        float h0 = __bfloat162float(__float2bfloat16(v0));
        float h1 = __bfloat162float(__float2bfloat16(v1));
        AH[m*36 + c2] = bfpack2(v0, v1);
        AL[m*36 + c2] = bfpack2(v0 - h0, v1 - h1);
    }
    // B fill: 256 px-rows x 32 c-pairs
    const float* ctx = contexts + (size_t)kb * E_ * HW_ + pix0;
    for (int i = tid; i < 256*32; i += 256) {
        int c2 = i >> 8, px = i & 255;
        float v0 = __ldg(ctx + (2*c2)*HW_ + px);
        float v1 = __ldg(ctx + (2*c2 + 1)*HW_ + px);
        float h0 = __bfloat162float(__float2bfloat16(v0));
        float h1 = __bfloat162float(__float2bfloat16(v1));
        BH[px*36 + c2] = bfpack2(v0, v1);
        BL[px*36 + c2] = bfpack2(v0 - h0, v1 - h1);
    }
    __syncthreads();

    int g = lane >> 2, tig = lane & 3;
    int m0 = wid * 16;
    int row0 = m0 + g, row1 = m0 + g + 8;

    uint32_t ah[4][4], al[4][4];
    #pragma unroll
    for (int kt = 0; kt < 4; kt++) {
        int base = kt*8 + tig;
        ah[kt][0] = AH[row0*36 + base];     ah[kt][1] = AH[row1*36 + base];
        ah[kt][2] = AH[row0*36 + base + 4]; ah[kt][3] = AH[row1*36 + base + 4];
        al[kt][0] = AL[row0*36 + base];     al[kt][1] = AL[row1*36 + base];
        al[kt][2] = AL[row0*36 + base + 4]; al[kt][3] = AL[row1*36 + base + 4];
    }

    int m8 = lane >> 3, r8 = lane & 7;
    uint32_t colb = ((m8 >> 1) << 3) + ((m8 & 1) << 2);
    uint32_t bhA0 = sb + (KP_BH + r8*36 + colb)*4;
    uint32_t blA0 = sb + (KP_BL + r8*36 + colb)*4;

    float bias0 = (row0 < 64) ? __ldg(&b_enc[row0]) : 0.f;
    float bias1 = (row1 < 64) ? __ldg(&b_enc[row1]) : 0.f;
    float* dst0 = (row0 < 64)
        ? (g_keys + PAD_ + (size_t)(kb*E_ + row0)*HW_ + pix0)
        : (g_proj + PAD_ + (size_t)(kb*E_ + row0 - 64)*HW_ + pix0);
    float* dst1 = (row1 < 64)
        ? (g_keys + PAD_ + (size_t)(kb*E_ + row1)*HW_ + pix0)
        : (g_proj + PAD_ + (size_t)(kb*E_ + row1 - 64)*HW_ + pix0);

    #pragma unroll 4
    for (int nt = 0; nt < 32; nt++) {
        uint32_t bh[8], bl[8];
        uint32_t aB = bhA0 + nt*1152;          // 8*36*4 bytes per nt
        uint32_t aL = blA0 + nt*1152;
        ldmat4(bh[0], bh[1], bh[2], bh[3], aB);       // kt 0,1
        ldmat4(bh[4], bh[5], bh[6], bh[7], aB + 64);  // kt 2,3
        ldmat4(bl[0], bl[1], bl[2], bl[3], aL);
        ldmat4(bl[4], bl[5], bl[6], bl[7], aL + 64);

        float d[4] = {0.f, 0.f, 0.f, 0.f};
        #pragma unroll
        for (int kt = 0; kt < 4; kt++) {
            mma16816(d, ah[kt], bh[2*kt], bh[2*kt+1]);
            mma16816(d, al[kt], bh[2*kt], bh[2*kt+1]);
            mma16816(d, ah[kt], bl[2*kt], bl[2*kt+1]);
        }
        int col = nt*8 + 2*tig;
        *(float2*)&dst0[col] = make_float2(d[0] + bias0, d[1] + bias0);
        *(float2*)&dst1[col] = make_float2(d[2] + bias1, d[3] + bias1);
    }
}

// ---------------- conv 3x3 (scalar f32x2, unchanged) ----------------
#define XROW 36
#define XD   (6*XROW)
#define WS_STRIDE 10
__global__ void __launch_bounds__(256) conv_kernel(const float* __restrict__ df) {
    extern __shared__ float sm[];
    float* xs = sm;                          // [16 d][6 rows][36 cols]
    ull*   wsu = (ull*)(sm + 16*XD);         // [16 d][32 jp][10] ull
    int bz = blockIdx.z;
    int b = bz >> 1, half = bz & 1;
    int w0 = blockIdx.x * 32, h0 = blockIdx.y * 4;
    int tid = threadIdx.x;
    int grp = tid >> 5, lane = tid & 31;
    int jp0 = grp * 4;
    int prow = lane >> 3, pcol0 = (lane & 7) * 4;

    ull acc[4][4];
    #pragma unroll
    for (int jp = 0; jp < 4; jp++)
        #pragma unroll
        for (int j = 0; j < 4; j++) acc[jp][j] = 0ull;

    int dbase = half * 64;
    for (int d0 = dbase; d0 < dbase + 64; d0 += 16) {
        __syncthreads();
        for (int i = tid; i < 16*XD; i += 256) {
            int d = i / XD, r = i - d*XD;
            int yy = r / XROW, xx = r - yy*XROW;
            float v = 0.f;
            if (xx < 34) {
                int gh = h0 + yy - 1, gw = w0 + xx - 1;
                if ((unsigned)gh < H_ && (unsigned)gw < W_)
                    v = df[(b*D_ + d0 + d)*HW_ + gh*W_ + gw];
            }
            xs[i] = v;
        }
        for (int i = tid; i < 16*32*9; i += 256) {
            int d = i / 288, r = i - d*288;
            int jp = r / 9, t = r - jp*9;
            int eo = jp * 2;
            float wlo = g_wveff[ eo   *(D_*9) + (d0 + d)*9 + t];
            float whi = g_wveff[(eo+1)*(D_*9) + (d0 + d)*9 + t];
            wsu[(d*32 + jp)*WS_STRIDE + t] = pack2(wlo, whi);
        }
        __syncthreads();

        for (int d = 0; d < 16; d++) {
            const float* xr = &xs[d*XD + prow*XROW + pcol0];
            ull xd[3][6];
            #pragma unroll
            for (int r = 0; r < 3; r++) {
                float4 f = *(const float4*)(xr + r*XROW);
                float2 g2 = *(const float2*)(xr + r*XROW + 4);
                xd[r][0] = dup2(f.x); xd[r][1] = dup2(f.y); xd[r][2] = dup2(f.z);
                xd[r][3] = dup2(f.w); xd[r][4] = dup2(g2.x); xd[r][5] = dup2(g2.y);
            }
            const ull* wb = wsu + (d*32 + jp0)*WS_STRIDE;
            #pragma unroll
            for (int jp = 0; jp < 4; jp++) {
                const ull* wp = wb + jp*WS_STRIDE;
                const longlong2* wp2 = (const longlong2*)wp;
                longlong2 wA = wp2[0], wB = wp2[1], wC = wp2[2], wD = wp2[3];
                ull wt[9] = {(ull)wA.x, (ull)wA.y, (ull)wB.x, (ull)wB.y,
                             (ull)wC.x, (ull)wC.y, (ull)wD.x, (ull)wD.y, wp[8]};
                #pragma unroll
                for (int t = 0; t < 9; t++) {
                    int tr = t / 3, tc = t - tr*3;
                    #pragma unroll
                    for (int j = 0; j < 4; j++)
                        fma2(acc[jp][j], xd[tr][tc + j], wt[t]);
                }
            }
        }
    }
    int pix = (h0 + prow)*W_ + w0 + pcol0;
    float* base = g_pvh + half*(B_*E_*HW_);
    #pragma unroll
    for (int jp = 0; jp < 4; jp++) {
        int eo = (jp0 + jp) * 2;
        float2 u[4];
        #pragma unroll
        for (int j = 0; j < 4; j++) u[j] = unpack2(acc[jp][j]);
        float4 vlo = make_float4(u[0].x, u[1].x, u[2].x, u[3].x);
        float4 vhi = make_float4(u[0].y, u[1].y, u[2].y, u[3].y);
        *(float4*)&base[(b*E_ + eo  )*HW_ + pix] = vlo;
        *(float4*)&base[(b*E_ + eo+1)*HW_ + pix] = vhi;
    }
}

// ---------------- attention: smem-tiled keys halo ----------------
// grid (3, 12, K*B), block 256 = 32x8 pixel tile.
#define KH_STRIDE 344
__global__ void __launch_bounds__(256) attn_kernel(const float* __restrict__ w_agg) {
    extern __shared__ float asm_[];
    float* kh = asm_;                  // [64 e][stride 344], halo 10x34=340 used
    float* swa = asm_ + 64*KH_STRIDE;  // [64]
    int tid = threadIdx.x;
    int kb = blockIdx.z;
    int b = kb & 1, k = kb >> 1;
    int w0 = blockIdx.x * 32, h0 = blockIdx.y * 8;
    int pxc = tid & 31, py = tid >> 5;

    if (tid < 64) swa[tid] = w_agg[tid];
    const float* keyb = g_keys + PAD_ + (size_t)(kb*E_)*HW_;
    for (int i = tid; i < 64*340; i += 256) {
        int e = i / 340, r = i - e*340;
        int hy = r / 34, hx = r - hy*34;
        int pix = (h0 + hy - 1)*W_ + (w0 + hx - 1);   // pad covers OOB
        kh[e*KH_STRIDE + r] = keyb[(size_t)e*HW_ + pix];
    }
    __syncthreads();

    int h = h0 + py, w = w0 + pxc;
    int pix = h*W_ + w;
    const float* qb = g_q + (size_t)(b*E_)*HW_ + pix;
    const float* khc = kh + (py + 1)*34 + (pxc + 1);

    float s[9];
    #pragma unroll
    for (int n = 0; n < 9; n++) s[n] = 0.f;

    #pragma unroll 2
    for (int e = 0; e < 64; e++) {
        float q = __ldg(qb + (size_t)e*HW_);
        float wa = swa[e];
        const float* kp = khc + e*KH_STRIDE;
        float t0 = tanh_hw(q + kp[-35]); float t1 = tanh_hw(q + kp[-34]);
        float t2 = tanh_hw(q + kp[-33]); float t3 = tanh_hw(q + kp[-1]);
        float t4 = tanh_hw(q + kp[0]);   float t5 = tanh_hw(q + kp[1]);
        float t6 = tanh_hw(q + kp[33]);  float t7 = tanh_hw(q + kp[34]);
        float t8 = tanh_hw(q + kp[35]);
        s[0] = fmaf(wa, t0, s[0]); s[1] = fmaf(wa, t1, s[1]);
        s[2] = fmaf(wa, t2, s[2]); s[3] = fmaf(wa, t3, s[3]);
        s[4] = fmaf(wa, t4, s[4]); s[5] = fmaf(wa, t5, s[5]);
        s[6] = fmaf(wa, t6, s[6]); s[7] = fmaf(wa, t7, s[7]);
        s[8] = fmaf(wa, t8, s[8]);
    }
    bool vt = h > 0, vb = h < H_-1, vl = w > 0, vr = w < W_-1;
    bool valid[9] = {vt&&vl, vt, vt&&vr, vl, true, vr, vb&&vl, vb, vb&&vr};
    float p[9], sum = 0.f;
    #pragma unroll
    for (int n = 0; n < 9; n++) {
        p[n] = valid[n] ? __expf(s[n]) : 0.f;
        sum += p[n];
    }
    float inv = 1.0f / sum;
    float* pd = g_p + (size_t)(b*HW_ + pix)*36 + k*9;
    #pragma unroll
    for (int n = 0; n < 9; n++) pd[n] = p[n] * inv;
}

// ---------------- output: pv halves + sum_k sum_n p * proj, bias, leaky ----------------
__global__ void out_kernel(const float* __restrict__ b_attn, float* __restrict__ out) {
    __shared__ float sp[32][37];
    int tid = threadIdx.x;
    int pixg0 = blockIdx.x * 32;
    int pl = tid & 31, ty = tid >> 5;

    for (int i = tid; i < 32*36; i += 256) {
        int a = i / 36, j = i - a*36;
        sp[a][j] = g_p[(pixg0 + a)*36 + j];
    }
    __syncthreads();

    int pg = pixg0 + pl;
    int b = pg / HW_;
    int pix = pg - b*HW_;
    int eo0 = ty * 8;
    const int off[9] = {-W_-1, -W_, -W_+1, -1, 0, 1, W_-1, W_, W_+1};

    float acc[8];
    #pragma unroll
    for (int j = 0; j < 8; j++)
        acc[j] = __ldg(&g_pvh[(b*E_ + eo0 + j)*HW_ + pix])
               + __ldg(&g_pvh[B_*E_*HW_ + (b*E_ + eo0 + j)*HW_ + pix]);

    #pragma unroll
    for (int k = 0; k < K_; k++) {
        const float* prb = g_proj + PAD_ + ((k*B_ + b)*E_ + eo0)*HW_ + pix;
        #pragma unroll
        for (int n = 0; n < 9; n++) {
            float pn = sp[pl][k*9 + n];
            int o = off[n];
            #pragma unroll
            for (int j = 0; j < 8; j++)
                acc[j] = fmaf(pn, __ldg(prb + j*HW_ + o), acc[j]);
        }
    }
    #pragma unroll
    for (int j = 0; j < 8; j++) {
        float v = acc[j] + __ldg(&g_bveff[eo0 + j]) + __ldg(&b_attn[eo0 + j]);
        v = (v >= 0.f) ? v : 0.2f * v;
        out[(b*E_ + eo0 + j)*HW_ + pix] = v;
    }
}

// ---------------- launch ----------------
extern "C" void kernel_launch(void* const* d_in, const int* in_sizes, int n_in,
                              void* d_out, int out_size) {
    const float* contexts = (const float*)d_in[0];
    const float* df       = (const float*)d_in[1];
    const float* w_enc    = (const float*)d_in[2];
    const float* b_enc    = (const float*)d_in[3];
    const float* w_dec    = (const float*)d_in[4];
    const float* b_dec    = (const float*)d_in[5];
    const float* w_agg    = (const float*)d_in[6];
    // d_in[7] = b_agg: cancels in softmax, unused
    const float* w_val    = (const float*)d_in[8];
    const float* b_val    = (const float*)d_in[9];
    const float* w_attn   = (const float*)d_in[10];
    const float* b_attn   = (const float*)d_in[11];
    float* out = (float*)d_out;

    int smq = Q_TOT32 * 4;                    // ~102 KB
    int smk = KP_TOT32 * 4;                   // ~108 KB
    int smc = 16*XD*4 + 16*32*WS_STRIDE*8;    // ~54 KB
    int sma = (64*KH_STRIDE + 64) * 4;        // ~86 KB
    cudaFuncSetAttribute(queries_mma,   cudaFuncAttributeMaxDynamicSharedMemorySize, smq);
    cudaFuncSetAttribute(keysproj_mma,  cudaFuncAttributeMaxDynamicSharedMemorySize, smk);
    cudaFuncSetAttribute(conv_kernel,   cudaFuncAttributeMaxDynamicSharedMemorySize, smc);
    cudaFuncSetAttribute(attn_kernel,   cudaFuncAttributeMaxDynamicSharedMemorySize, sma);

    prep_wveff<<<288, 256>>>(w_attn, w_val);
    prep_bveff<<<1, 64>>>(w_attn, b_val);
    queries_mma<<<dim3(HW_/128, B_), 256, smq>>>(df, w_dec, b_dec);
    keysproj_mma<<<dim3(HW_/256, K_*B_), 256, smk>>>(contexts, w_enc, b_enc, w_attn);
    conv_kernel<<<dim3(3, 24, B_*2), 256, smc>>>(df);
    attn_kernel<<<dim3(3, 12, K_*B_), 256, sma>>>(w_agg);
    out_kernel<<<(B_*HW_)/32, 256>>>(b_attn, out);
}

// round 7
// speedup vs baseline: 2.0727x; 1.2176x over previous
#include <cuda_runtime.h>
#include <cuda_bf16.h>
#include <cstdint>

#define E_ 64
#define D_ 128
#define K_ 4
#define B_ 2
#define H_ 96
#define W_ 96
#define HW_ (H_*W_)
#define PAD_ 128

typedef unsigned long long ull;

// ---------------- scratch (static device globals) ----------------
__device__ float g_keys[K_*B_*E_*HW_ + 2*PAD_];
__device__ float g_proj[K_*B_*E_*HW_ + 2*PAD_];
__device__ float g_q   [B_*E_*HW_];
__device__ float g_pvh [2*B_*E_*HW_];             // conv partials, 2 D-halves
__device__ float g_p   [B_*HW_*36];
__device__ float g_wveff[E_*D_*9];
__device__ float g_bveff[E_];
__device__ uint32_t g_wvh[8*64*72];               // packed bf16x2 conv weights (hi)
__device__ uint32_t g_wvl[8*64*72];               // (lo)
__device__ uint32_t g_dfh[B_*64*HW_];             // df packed bf16x2 channel pairs (hi)
__device__ uint32_t g_dfl[B_*64*HW_];             // (lo)

// ---------------- helpers ----------------
__device__ __forceinline__ float tanh_hw(float x) {
    float r; asm("tanh.approx.f32 %0, %1;" : "=f"(r) : "f"(x)); return r;
}
__device__ __forceinline__ unsigned bfpack2(float a, float b) {
    __nv_bfloat162 t = __floats2bfloat162_rn(a, b);
    return *(unsigned*)&t;
}
__device__ __forceinline__ void mma16816(float* d, const uint32_t* a,
                                         uint32_t b0, uint32_t b1) {
    asm volatile(
        "mma.sync.aligned.m16n8k16.row.col.f32.bf16.bf16.f32 "
        "{%0,%1,%2,%3}, {%4,%5,%6,%7}, {%8,%9}, {%0,%1,%2,%3};"
        : "+f"(d[0]), "+f"(d[1]), "+f"(d[2]), "+f"(d[3])
        : "r"(a[0]), "r"(a[1]), "r"(a[2]), "r"(a[3]), "r"(b0), "r"(b1));
}
__device__ __forceinline__ void ldmat4(uint32_t& a, uint32_t& b, uint32_t& c,
                                       uint32_t& d, uint32_t saddr) {
    asm volatile("ldmatrix.sync.aligned.m8n8.x4.shared.b16 {%0,%1,%2,%3}, [%4];"
                 : "=r"(a), "=r"(b), "=r"(c), "=r"(d) : "r"(saddr));
}
__device__ __forceinline__ uint32_t smem_u32(const void* p) {
    uint32_t a;
    asm("{ .reg .u64 t; cvta.to.shared.u64 t, %1; cvt.u32.u64 %0, t; }" : "=r"(a) : "l"(p));
    return a;
}

// ---------------- prep kernels ----------------
__global__ void prep_wveff(const float* __restrict__ w_attn, const float* __restrict__ w_val) {
    int o = blockIdx.x * 256 + threadIdx.x;          // 73728 total, exact
    int eo = o / (D_*9);
    int r  = o - eo * (D_*9);
    const float* wa = w_attn + eo * ((K_+1)*E_);
    float a = 0.f;
    #pragma unroll 8
    for (int e = 0; e < E_; e++) a = fmaf(wa[e], w_val[e*(D_*9) + r], a);
    g_wveff[o] = a;
}

__global__ void prep_bveff(const float* __restrict__ w_attn, const float* __restrict__ b_val) {
    int eo = threadIdx.x;
    const float* wa = w_attn + eo * ((K_+1)*E_);
    float a = 0.f;
    for (int e = 0; e < E_; e++) a = fmaf(wa[e], b_val[e], a);
    g_bveff[eo] = a;
}

// pack conv weights into A-smem layout: [chunk 8][eo 64][t*8+cp], bf16 hi/lo split
__global__ void prep_wvpack() {
    int o = blockIdx.x * 256 + threadIdx.x;          // 36864 exact
    int chunk = o / (64*72);
    int r = o - chunk*(64*72);
    int eo = r / 72;
    int idx = r - eo*72;
    int t = idx >> 3, cp = idx & 7;
    int d0 = chunk*16;
    float v0 = g_wveff[eo*(D_*9) + (d0 + 2*cp)*9 + t];
    float v1 = g_wveff[eo*(D_*9) + (d0 + 2*cp + 1)*9 + t];
    float h0 = __bfloat162float(__float2bfloat16(v0));
    float h1 = __bfloat162float(__float2bfloat16(v1));
    g_wvh[o] = bfpack2(v0, v1);
    g_wvl[o] = bfpack2(v0 - h0, v1 - h1);
}

// split df into bf16 hi/lo, packed across channel pairs: [b][cp 64][pix]
__global__ void prep_split_df(const float* __restrict__ df) {
    int o = blockIdx.x * 256 + threadIdx.x;          // B*64*HW = 1179648 exact
    int b = o / (64*HW_);
    int r = o - b*(64*HW_);
    int cp = r / HW_;
    int pix = r - cp*HW_;
    float v0 = df[(b*D_ + 2*cp)*HW_ + pix];
    float v1 = df[(b*D_ + 2*cp + 1)*HW_ + pix];
    float h0 = __bfloat162float(__float2bfloat16(v0));
    float h1 = __bfloat162float(__float2bfloat16(v1));
    g_dfh[o] = bfpack2(v0, v1);
    g_dfl[o] = bfpack2(v0 - h0, v1 - h1);
}

// ---------------- queries via mma.sync bf16 3-term split ----------------
// D[64 m][128 px] = w_dec[64,128] @ df[128,128px]. grid (72, B), block 256.
#define QA_H 0
#define QA_L 4352            // 64*68
#define QB_H 8704
#define QB_L 17408           // + 128*68
#define Q_TOT32 26112        // *4 = 104448 bytes

__global__ void __launch_bounds__(256) queries_mma(
        const float* __restrict__ df,
        const float* __restrict__ w_dec,
        const float* __restrict__ b_dec) {
    extern __shared__ uint32_t sm32[];
    uint32_t* AH = sm32 + QA_H;
    uint32_t* AL = sm32 + QA_L;
    uint32_t* BH = sm32 + QB_H;
    uint32_t* BL = sm32 + QB_L;
    uint32_t sb = smem_u32(sm32);
    int tid = threadIdx.x, wid = tid >> 5, lane = tid & 31;
    int b = blockIdx.y, pix0 = blockIdx.x * 128;

    for (int i = tid; i < 64*64; i += 256) {
        int m = i >> 6, c2 = i & 63;
        float v0 = w_dec[m*D_ + 2*c2], v1 = w_dec[m*D_ + 2*c2 + 1];
        float h0 = __bfloat162float(__float2bfloat16(v0));
        float h1 = __bfloat162float(__float2bfloat16(v1));
        AH[m*68 + c2] = bfpack2(v0, v1);
        AL[m*68 + c2] = bfpack2(v0 - h0, v1 - h1);
    }
    const uint32_t* dfhb = g_dfh + (size_t)b * 64 * HW_ + pix0;
    const uint32_t* dflb = g_dfl + (size_t)b * 64 * HW_ + pix0;
    for (int i = tid; i < 128*64; i += 256) {
        int c2 = i >> 7, px = i & 127;
        BH[px*68 + c2] = __ldg(dfhb + (size_t)c2*HW_ + px);
        BL[px*68 + c2] = __ldg(dflb + (size_t)c2*HW_ + px);
    }
    __syncthreads();

    int g = lane >> 2, tig = lane & 3;
    int mslab = wid & 3, nhalf = wid >> 2;
    int row0 = mslab*16 + g, row1 = row0 + 8;

    uint32_t ah[8][4], al[8][4];
    #pragma unroll
    for (int kt = 0; kt < 8; kt++) {
        int base = kt*8 + tig;
        ah[kt][0] = AH[row0*68 + base];     ah[kt][1] = AH[row1*68 + base];
        ah[kt][2] = AH[row0*68 + base + 4]; ah[kt][3] = AH[row1*68 + base + 4];
        al[kt][0] = AL[row0*68 + base];     al[kt][1] = AL[row1*68 + base];
        al[kt][2] = AL[row0*68 + base + 4]; al[kt][3] = AL[row1*68 + base + 4];
    }

    int m8 = lane >> 3, r8 = lane & 7;
    uint32_t colb = ((m8 >> 1) << 3) + ((m8 & 1) << 2);
    uint32_t bhA0 = sb + (QB_H + r8*68 + colb)*4 + nhalf*8*2176;
    uint32_t blA0 = sb + (QB_L + r8*68 + colb)*4 + nhalf*8*2176;

    float bias0 = __ldg(&b_dec[row0]);
    float bias1 = __ldg(&b_dec[row1]);
    float* dst0 = g_q + (size_t)(b*E_ + row0)*HW_ + pix0;
    float* dst1 = g_q + (size_t)(b*E_ + row1)*HW_ + pix0;

    #pragma unroll
    for (int nt = 0; nt < 8; nt++) {
        uint32_t bh[16], bl[16];
        uint32_t aB = bhA0 + nt*2176;
        uint32_t aL = blA0 + nt*2176;
        ldmat4(bh[0], bh[1], bh[2], bh[3], aB);
        ldmat4(bh[4], bh[5], bh[6], bh[7], aB + 64);
        ldmat4(bh[8], bh[9], bh[10], bh[11], aB + 128);
        ldmat4(bh[12], bh[13], bh[14], bh[15], aB + 192);
        ldmat4(bl[0], bl[1], bl[2], bl[3], aL);
        ldmat4(bl[4], bl[5], bl[6], bl[7], aL + 64);
        ldmat4(bl[8], bl[9], bl[10], bl[11], aL + 128);
        ldmat4(bl[12], bl[13], bl[14], bl[15], aL + 192);

        float d[4] = {0.f, 0.f, 0.f, 0.f};
        #pragma unroll
        for (int kt = 0; kt < 8; kt++) {
            mma16816(d, ah[kt], bh[2*kt], bh[2*kt+1]);
            mma16816(d, al[kt], bh[2*kt], bh[2*kt+1]);
            mma16816(d, ah[kt], bl[2*kt], bl[2*kt+1]);
        }
        int col = (nhalf*8 + nt)*8 + 2*tig;
        *(float2*)&dst0[col] = make_float2(d[0] + bias0, d[1] + bias0);
        *(float2*)&dst1[col] = make_float2(d[2] + bias1, d[3] + bias1);
    }
}

// ---------------- keys + proj via mma.sync bf16 3-term split + ldmatrix ----------------
#define KP_AH 0
#define KP_AL 4608           // 128*36
#define KP_BH 9216
#define KP_BL 18432          // + 256*36
#define KP_TOT32 27648       // *4 = 110592 bytes

__global__ void __launch_bounds__(256) keysproj_mma(
        const float* __restrict__ contexts,
        const float* __restrict__ w_enc,
        const float* __restrict__ b_enc,
        const float* __restrict__ w_attn) {
    extern __shared__ uint32_t sm32[];
    uint32_t* AH = sm32 + KP_AH;
    uint32_t* AL = sm32 + KP_AL;
    uint32_t* BH = sm32 + KP_BH;
    uint32_t* BL = sm32 + KP_BL;
    uint32_t sb = smem_u32(sm32);
    int tid = threadIdx.x, wid = tid >> 5, lane = tid & 31;
    int kb = blockIdx.y, k = kb >> 1;
    int pix0 = blockIdx.x * 256;

    for (int i = tid; i < 128*32; i += 256) {
        int m = i >> 5, c2 = i & 31;
        const float* row = (m < 64) ? (w_enc + m*64)
                                    : (w_attn + (m - 64)*((K_+1)*E_) + (k + 1)*E_);
        float v0 = row[2*c2], v1 = row[2*c2 + 1];
        float h0 = __bfloat162float(__float2bfloat16(v0));
        float h1 = __bfloat162float(__float2bfloat16(v1));
        AH[m*36 + c2] = bfpack2(v0, v1);
        AL[m*36 + c2] = bfpack2(v0 - h0, v1 - h1);
    }
    const float* ctx = contexts + (size_t)kb * E_ * HW_ + pix0;
    for (int i = tid; i < 256*32; i += 256) {
        int c2 = i >> 8, px = i & 255;
        float v0 = __ldg(ctx + (2*c2)*HW_ + px);
        float v1 = __ldg(ctx + (2*c2 + 1)*HW_ + px);
        float h0 = __bfloat162float(__float2bfloat16(v0));
        float h1 = __bfloat162float(__float2bfloat16(v1));
        BH[px*36 + c2] = bfpack2(v0, v1);
        BL[px*36 + c2] = bfpack2(v0 - h0, v1 - h1);
    }
    __syncthreads();

    int g = lane >> 2, tig = lane & 3;
    int m0 = wid * 16;
    int row0 = m0 + g, row1 = m0 + g + 8;

    uint32_t ah[4][4], al[4][4];
    #pragma unroll
    for (int kt = 0; kt < 4; kt++) {
        int base = kt*8 + tig;
        ah[kt][0] = AH[row0*36 + base];     ah[kt][1] = AH[row1*36 + base];
        ah[kt][2] = AH[row0*36 + base + 4]; ah[kt][3] = AH[row1*36 + base + 4];
        al[kt][0] = AL[row0*36 + base];     al[kt][1] = AL[row1*36 + base];
        al[kt][2] = AL[row0*36 + base + 4]; al[kt][3] = AL[row1*36 + base + 4];
    }

    int m8 = lane >> 3, r8 = lane & 7;
    uint32_t colb = ((m8 >> 1) << 3) + ((m8 & 1) << 2);
    uint32_t bhA0 = sb + (KP_BH + r8*36 + colb)*4;
    uint32_t blA0 = sb + (KP_BL + r8*36 + colb)*4;

    float bias0 = (row0 < 64) ? __ldg(&b_enc[row0]) : 0.f;
    float bias1 = (row1 < 64) ? __ldg(&b_enc[row1]) : 0.f;
    float* dst0 = (row0 < 64)
        ? (g_keys + PAD_ + (size_t)(kb*E_ + row0)*HW_ + pix0)
        : (g_proj + PAD_ + (size_t)(kb*E_ + row0 - 64)*HW_ + pix0);
    float* dst1 = (row1 < 64)
        ? (g_keys + PAD_ + (size_t)(kb*E_ + row1)*HW_ + pix0)
        : (g_proj + PAD_ + (size_t)(kb*E_ + row1 - 64)*HW_ + pix0);

    #pragma unroll 4
    for (int nt = 0; nt < 32; nt++) {
        uint32_t bh[8], bl[8];
        uint32_t aB = bhA0 + nt*1152;
        uint32_t aL = blA0 + nt*1152;
        ldmat4(bh[0], bh[1], bh[2], bh[3], aB);
        ldmat4(bh[4], bh[5], bh[6], bh[7], aB + 64);
        ldmat4(bl[0], bl[1], bl[2], bl[3], aL);
        ldmat4(bl[4], bl[5], bl[6], bl[7], aL + 64);

        float d[4] = {0.f, 0.f, 0.f, 0.f};
        #pragma unroll
        for (int kt = 0; kt < 4; kt++) {
            mma16816(d, ah[kt], bh[2*kt], bh[2*kt+1]);
            mma16816(d, al[kt], bh[2*kt], bh[2*kt+1]);
            mma16816(d, ah[kt], bl[2*kt], bl[2*kt+1]);
        }
        int col = nt*8 + 2*tig;
        *(float2*)&dst0[col] = make_float2(d[0] + bias0, d[1] + bias0);
        *(float2*)&dst1[col] = make_float2(d[2] + bias1, d[3] + bias1);
    }
}

// ---------------- conv 3x3 via implicit-GEMM mma.sync ----------------
// Tile: 8 rows x 32 cols px, M=64 eo, K=576 (d-half x 9 taps). grid (3,12,B*2).
// smem u32 offsets:
#define CV_AH 0
#define CV_AL 4864           // 64*76
#define CV_HH 9728
#define CV_HL 13808          // + 340*12
#define CV_TOT32 17888       // *4 = 71552 bytes

__global__ void __launch_bounds__(256) conv_mma() {
    extern __shared__ uint32_t cs[];
    uint32_t sb = smem_u32(cs);
    int tid = threadIdx.x, wid = tid >> 5, lane = tid & 31;
    int bz = blockIdx.z;
    int b = bz >> 1, half = bz & 1;
    int w0 = blockIdx.x * 32, h0 = blockIdx.y * 8;
    int mslab = wid & 3, nh = wid >> 2;
    int m0 = mslab * 16;
    int g8 = lane >> 3, r8 = lane & 7;
    int tg = lane >> 2, tig = lane & 3;

    // lane-const ldmatrix base addresses (bytes)
    uint32_t aA = sb + (CV_AH + ((m0 + (g8 & 1)*8 + r8)*76 + (g8 >> 1)*4))*4;
    uint32_t aB = sb + CV_HH*4
                + (34 + nh*16 + (g8 >> 1)*8 + r8 + 1)*48 + (g8 & 1)*16;

    float d[16][4];
    #pragma unroll
    for (int i = 0; i < 16; i++)
        #pragma unroll
        for (int j = 0; j < 4; j++) d[i][j] = 0.f;

    for (int chunk = 0; chunk < 4; chunk++) {
        int d0 = half*64 + chunk*16;
        __syncthreads();
        // A fill (pure u32 copy from pre-packed weights)
        {
            const uint32_t* srcH = g_wvh + (half*4 + chunk)*4608;
            const uint32_t* srcL = g_wvl + (half*4 + chunk)*4608;
            for (int i = tid; i < 4608; i += 256) {
                int m = i / 72, c = i - m*72;
                cs[CV_AH + m*76 + c] = srcH[i];
                cs[CV_AL + m*76 + c] = srcL[i];
            }
        }
        // halo fill: 340 positions x 8 c-pairs, zero OOB
        {
            int cp0 = d0 >> 1;
            for (int i = tid; i < 2720; i += 256) {
                int cp = i / 340, hp = i - cp*340;
                int hy = hp / 34, hx = hp - hy*34;
                int gh = h0 + hy - 1, gw = w0 + hx - 1;
                uint32_t vh = 0, vl = 0;
                if ((unsigned)gh < H_ && (unsigned)gw < W_) {
                    int idx = (b*64 + cp0 + cp)*HW_ + gh*W_ + gw;
                    vh = g_dfh[idx]; vl = g_dfl[idx];
                }
                cs[CV_HH + hp*12 + cp] = vh;
                cs[CV_HL + hp*12 + cp] = vl;
            }
        }
        __syncthreads();

        for (int t = 0; t < 9; t++) {
            uint32_t ah[4], al[4];
            ldmat4(ah[0], ah[1], ah[2], ah[3], aA + t*32);
            ldmat4(al[0], al[1], al[2], al[3], aA + 19456 + t*32);
            int t3 = t / 3;
            int toff = (t3*34 + (t - t3*3) - 35) * 48;     // (dy*34+dx)*48
            uint32_t bbase = aB + toff;
            #pragma unroll
            for (int ntp = 0; ntp < 8; ntp++) {
                uint32_t ba = bbase + ntp*1632;            // 34*48
                uint32_t bh[4], bl[4];
                ldmat4(bh[0], bh[1], bh[2], bh[3], ba);
                ldmat4(bl[0], bl[1], bl[2], bl[3], ba + 16320);
                mma16816(d[ntp*2],     ah, bh[0], bh[1]);
                mma16816(d[ntp*2],     al, bh[0], bh[1]);
                mma16816(d[ntp*2],     ah, bl[0], bl[1]);
                mma16816(d[ntp*2 + 1], ah, bh[2], bh[3]);
                mma16816(d[ntp*2 + 1], al, bh[2], bh[3]);
                mma16816(d[ntp*2 + 1], ah, bl[2], bl[3]);
            }
        }
    }
    // epilogue: partials into g_pvh[half]
    float* base = g_pvh + half*(B_*E_*HW_);
    int eo0 = m0 + tg;
    #pragma unroll
    for (int ntp = 0; ntp < 8; ntp++) {
        int pixrow = (h0 + ntp)*W_ + w0 + nh*16;
        #pragma unroll
        for (int hb = 0; hb < 2; hb++) {
            float* dd = d[ntp*2 + hb];
            int col = pixrow + hb*8 + 2*tig;
            *(float2*)&base[(b*E_ + eo0    )*HW_ + col] = make_float2(dd[0], dd[1]);
            *(float2*)&base[(b*E_ + eo0 + 8)*HW_ + col] = make_float2(dd[2], dd[3]);
        }
    }
}

// ---------------- attention: smem-tiled keys halo ----------------
#define KH_STRIDE 344
__global__ void __launch_bounds__(256) attn_kernel(const float* __restrict__ w_agg) {
    extern __shared__ float asm_[];
    float* kh = asm_;                  // [64 e][stride 344]
    float* swa = asm_ + 64*KH_STRIDE;  // [64]
    int tid = threadIdx.x;
    int kb = blockIdx.z;
    int b = kb & 1, k = kb >> 1;
    int w0 = blockIdx.x * 32, h0 = blockIdx.y * 8;
    int pxc = tid & 31, py = tid >> 5;

    if (tid < 64) swa[tid] = w_agg[tid];
    const float* keyb = g_keys + PAD_ + (size_t)(kb*E_)*HW_;
    for (int i = tid; i < 64*340; i += 256) {
        int e = i / 340, r = i - e*340;
        int hy = r / 34, hx = r - hy*34;
        int pix = (h0 + hy - 1)*W_ + (w0 + hx - 1);   // pad covers OOB
        kh[e*KH_STRIDE + r] = keyb[(size_t)e*HW_ + pix];
    }
    __syncthreads();

    int h = h0 + py, w = w0 + pxc;
    int pix = h*W_ + w;
    const float* qb = g_q + (size_t)(b*E_)*HW_ + pix;
    const float* khc = kh + (py + 1)*34 + (pxc + 1);

    float s[9];
    #pragma unroll
    for (int n = 0; n < 9; n++) s[n] = 0.f;

    #pragma unroll 2
    for (int e = 0; e < 64; e++) {
        float q = __ldg(qb + (size_t)e*HW_);
        float wa = swa[e];
        const float* kp = khc + e*KH_STRIDE;
        float t0 = tanh_hw(q + kp[-35]); float t1 = tanh_hw(q + kp[-34]);
        float t2 = tanh_hw(q + kp[-33]); float t3 = tanh_hw(q + kp[-1]);
        float t4 = tanh_hw(q + kp[0]);   float t5 = tanh_hw(q + kp[1]);
        float t6 = tanh_hw(q + kp[33]);  float t7 = tanh_hw(q + kp[34]);
        float t8 = tanh_hw(q + kp[35]);
        s[0] = fmaf(wa, t0, s[0]); s[1] = fmaf(wa, t1, s[1]);
        s[2] = fmaf(wa, t2, s[2]); s[3] = fmaf(wa, t3, s[3]);
        s[4] = fmaf(wa, t4, s[4]); s[5] = fmaf(wa, t5, s[5]);
        s[6] = fmaf(wa, t6, s[6]); s[7] = fmaf(wa, t7, s[7]);
        s[8] = fmaf(wa, t8, s[8]);
    }
    bool vt = h > 0, vb = h < H_-1, vl = w > 0, vr = w < W_-1;
    bool valid[9] = {vt&&vl, vt, vt&&vr, vl, true, vr, vb&&vl, vb, vb&&vr};
    float p[9], sum = 0.f;
    #pragma unroll
    for (int n = 0; n < 9; n++) {
        p[n] = valid[n] ? __expf(s[n]) : 0.f;
        sum += p[n];
    }
    float inv = 1.0f / sum;
    float* pd = g_p + (size_t)(b*HW_ + pix)*36 + k*9;
    #pragma unroll
    for (int n = 0; n < 9; n++) pd[n] = p[n] * inv;
}

// ---------------- output: pv halves + sum_k sum_n p * proj, bias, leaky ----------------
__global__ void out_kernel(const float* __restrict__ b_attn, float* __restrict__ out) {
    __shared__ float sp[32][37];
    int tid = threadIdx.x;
    int pixg0 = blockIdx.x * 32;
    int pl = tid & 31, ty = tid >> 5;

    for (int i = tid; i < 32*36; i += 256) {
        int a = i / 36, j = i - a*36;
        sp[a][j] = g_p[(pixg0 + a)*36 + j];
    }
    __syncthreads();

    int pg = pixg0 + pl;
    int b = pg / HW_;
    int pix = pg - b*HW_;
    int eo0 = ty * 8;
    const int off[9] = {-W_-1, -W_, -W_+1, -1, 0, 1, W_-1, W_, W_+1};

    float acc[8];
    #pragma unroll
    for (int j = 0; j < 8; j++)
        acc[j] = __ldg(&g_pvh[(b*E_ + eo0 + j)*HW_ + pix])
               + __ldg(&g_pvh[B_*E_*HW_ + (b*E_ + eo0 + j)*HW_ + pix]);

    #pragma unroll
    for (int k = 0; k < K_; k++) {
        const float* prb = g_proj + PAD_ + ((k*B_ + b)*E_ + eo0)*HW_ + pix;
        #pragma unroll
        for (int n = 0; n < 9; n++) {
            float pn = sp[pl][k*9 + n];
            int o = off[n];
            #pragma unroll
            for (int j = 0; j < 8; j++)
                acc[j] = fmaf(pn, __ldg(prb + j*HW_ + o), acc[j]);
        }
    }
    #pragma unroll
    for (int j = 0; j < 8; j++) {
        float v = acc[j] + __ldg(&g_bveff[eo0 + j]) + __ldg(&b_attn[eo0 + j]);
        v = (v >= 0.f) ? v : 0.2f * v;
        out[(b*E_ + eo0 + j)*HW_ + pix] = v;
    }
}

// ---------------- launch ----------------
extern "C" void kernel_launch(void* const* d_in, const int* in_sizes, int n_in,
                              void* d_out, int out_size) {
    const float* contexts = (const float*)d_in[0];
    const float* df       = (const float*)d_in[1];
    const float* w_enc    = (const float*)d_in[2];
    const float* b_enc    = (const float*)d_in[3];
    const float* w_dec    = (const float*)d_in[4];
    const float* b_dec    = (const float*)d_in[5];
    const float* w_agg    = (const float*)d_in[6];
    // d_in[7] = b_agg: cancels in softmax, unused
    const float* w_val    = (const float*)d_in[8];
    const float* b_val    = (const float*)d_in[9];
    const float* w_attn   = (const float*)d_in[10];
    const float* b_attn   = (const float*)d_in[11];
    float* out = (float*)d_out;

    int smq = Q_TOT32 * 4;
    int smk = KP_TOT32 * 4;
    int smc = CV_TOT32 * 4;
    int sma = (64*KH_STRIDE + 64) * 4;
    cudaFuncSetAttribute(queries_mma,   cudaFuncAttributeMaxDynamicSharedMemorySize, smq);
    cudaFuncSetAttribute(keysproj_mma,  cudaFuncAttributeMaxDynamicSharedMemorySize, smk);
    cudaFuncSetAttribute(conv_mma,      cudaFuncAttributeMaxDynamicSharedMemorySize, smc);
    cudaFuncSetAttribute(attn_kernel,   cudaFuncAttributeMaxDynamicSharedMemorySize, sma);

    prep_wveff<<<288, 256>>>(w_attn, w_val);
    prep_bveff<<<1, 64>>>(w_attn, b_val);
    prep_wvpack<<<144, 256>>>();
    prep_split_df<<<(B_*64*HW_)/256, 256>>>(df);
    queries_mma<<<dim3(HW_/128, B_), 256, smq>>>(df, w_dec, b_dec);
    keysproj_mma<<<dim3(HW_/256, K_*B_), 256, smk>>>(contexts, w_enc, b_enc, w_attn);
    conv_mma<<<dim3(3, 12, B_*2), 256, smc>>>();
    attn_kernel<<<dim3(3, 12, K_*B_), 256, sma>>>(w_agg);
    out_kernel<<<(B_*HW_)/32, 256>>>(b_attn, out);
}